// round 7
// baseline (speedup 1.0000x reference)
#include <cuda_runtime.h>
#include <math.h>

#define S 48
#define BATCH 16
#define HID 512
#define HDIR 256
#define NL 16
#define M_ROWS 768            // S*BATCH
#define VOUT 32000

// ---------------- device scratch (static, no allocation) ----------------
__device__ float g_act0[M_ROWS * HID];
__device__ float g_act1[M_ROWS * HID];
__device__ float g_G[M_ROWS * 2048];
__device__ float g_hping[8192];
__device__ float g_hpong[8192];
__device__ float g_dech0[NL * 8192];
__device__ float g_decc0[NL * 8192];
// barrier area: group counters at [g*256] g<16, root at [16*256],
// per-CTA release flags at [(17+cta)*256]. 1KB stride -> distinct L2 lines/slices.
__device__ unsigned g_bar[(17 + 128) * 256];

// ---------------- flat tree grid barrier: 1 poller per line, no sleep ----------------
__device__ __forceinline__ void gbar2(unsigned epoch) {
    __syncthreads();
    if (threadIdx.x == 0) {
        __threadfence();                      // drain this CTA's h/ds stores to L2
        unsigned old;
        unsigned* gcnt = &g_bar[(blockIdx.x >> 3) * 256];
        asm volatile("atom.release.gpu.global.add.u32 %0,[%1],%2;"
                     : "=r"(old) : "l"(gcnt), "r"(1u) : "memory");
        if (old == 7u) {
            asm volatile("st.relaxed.gpu.global.u32 [%0],%1;" :: "l"(gcnt), "r"(0u) : "memory");
            unsigned* rcnt = &g_bar[16 * 256];
            asm volatile("atom.release.gpu.global.add.u32 %0,[%1],%2;"
                         : "=r"(old) : "l"(rcnt), "r"(1u) : "memory");
            if (old == 15u) {
                asm volatile("st.relaxed.gpu.global.u32 [%0],%1;" :: "l"(rcnt), "r"(0u) : "memory");
                __threadfence();              // order resets before release flags
#pragma unroll 8
                for (int i = 0; i < 128; ++i)
                    asm volatile("st.relaxed.gpu.global.u32 [%0],%1;"
                                 :: "l"(&g_bar[(17 + i) * 256]), "r"(epoch) : "memory");
            }
        }
        const unsigned* myf = &g_bar[(17 + blockIdx.x) * 256];
        unsigned v;
        do {
            asm volatile("ld.relaxed.gpu.global.u32 %0,[%1];" : "=r"(v) : "l"(myf) : "memory");
        } while ((int)(v - epoch) < 0);
        __threadfence();
    }
    __syncthreads();
}

// ---------------- embedding gather ----------------
__global__ void embed_k(const float* __restrict__ emb, const int* __restrict__ ids,
                        float* __restrict__ out) {
    int tb = blockIdx.x;            // t*16+b
    int t = tb >> 4, b = tb & 15;
    int id = ids[b * S + t];
    const float4* src = reinterpret_cast<const float4*>(emb) + (size_t)id * (HID / 4);
    float4* dst = reinterpret_cast<float4*>(out) + (size_t)tb * (HID / 4);
    dst[threadIdx.x] = src[threadIdx.x];
}

// ---------------- C[m][n] = A[m][:512] . W[n][:512] + bias[n], M=768, K=512 ----------------
__global__ __launch_bounds__(256) void gemm_k(
    const float* __restrict__ A, const float* __restrict__ W,
    const float* __restrict__ bias, float* __restrict__ C,
    size_t sB, size_t sT, size_t sN) {
    __shared__ float4 smem4[(16 * 68 * 2) / 4];
    float* As = (float*)smem4;
    float* Ws = As + 16 * 68;
    int tid = threadIdx.x;
    int tx = tid & 15, ty = tid >> 4;
    int n0 = blockIdx.x * 64, m0 = blockIdx.y * 64;
    int r = tid >> 2, kq = (tid & 3) * 4;

    float acc[16];
#pragma unroll
    for (int i = 0; i < 16; ++i) acc[i] = 0.f;

    for (int k0 = 0; k0 < 512; k0 += 16) {
        float4 a = *reinterpret_cast<const float4*>(A + (size_t)(m0 + r) * 512 + k0 + kq);
        float4 w = *reinterpret_cast<const float4*>(W + (size_t)(n0 + r) * 512 + k0 + kq);
        As[(kq + 0) * 68 + r] = a.x; As[(kq + 1) * 68 + r] = a.y;
        As[(kq + 2) * 68 + r] = a.z; As[(kq + 3) * 68 + r] = a.w;
        Ws[(kq + 0) * 68 + r] = w.x; Ws[(kq + 1) * 68 + r] = w.y;
        Ws[(kq + 2) * 68 + r] = w.z; Ws[(kq + 3) * 68 + r] = w.w;
        __syncthreads();
#pragma unroll
        for (int kk = 0; kk < 16; ++kk) {
            float4 av = *reinterpret_cast<const float4*>(&As[kk * 68 + ty * 4]);
            float4 wv = *reinterpret_cast<const float4*>(&Ws[kk * 68 + tx * 4]);
            acc[0]  += av.x * wv.x; acc[1]  += av.x * wv.y; acc[2]  += av.x * wv.z; acc[3]  += av.x * wv.w;
            acc[4]  += av.y * wv.x; acc[5]  += av.y * wv.y; acc[6]  += av.y * wv.z; acc[7]  += av.y * wv.w;
            acc[8]  += av.z * wv.x; acc[9]  += av.z * wv.y; acc[10] += av.z * wv.z; acc[11] += av.z * wv.w;
            acc[12] += av.w * wv.x; acc[13] += av.w * wv.y; acc[14] += av.w * wv.z; acc[15] += av.w * wv.w;
        }
        __syncthreads();
    }
#pragma unroll
    for (int i = 0; i < 4; ++i) {
        int m = m0 + ty * 4 + i;
        int b = m & 15, t = m >> 4;
#pragma unroll
        for (int jx = 0; jx < 4; ++jx) {
            int n = n0 + tx * 4 + jx;
            C[(size_t)b * sB + (size_t)t * sT + (size_t)n * sN] = acc[i * 4 + jx] + bias[n];
        }
    }
}

__device__ __forceinline__ float sigm(float x) { return 1.f / (1.f + expf(-x)); }

// ======================= persistent decoder layer =======================
// 128 CTAs x 256 threads. CTA owns 4 j (x 4 gates = 16 rows of 2048).
__global__ __launch_bounds__(256, 1) void dec_layer_k(
    const float* __restrict__ Whh,             // (2048,512)
    const float* __restrict__ G, float* __restrict__ ds_out,
    float* __restrict__ hp, float* __restrict__ hq,
    const float* __restrict__ dh, const float* __restrict__ dc) {
    __shared__ float4 h4[2048];                // 32KB; overlaid by red/gsum after use
    __shared__ float c_sm[64];
    __shared__ unsigned s_base;
    float* red = reinterpret_cast<float*>(h4); // [kc*256 + rid*16 + b]
    float* gsum = red + 4096;                  // 256 floats

    int tid = threadIdx.x;
    int kc = tid >> 4;
    int rid = tid & 15;
    int g = rid >> 2, jj = rid & 3;
    int j0 = blockIdx.x * 4;
    int row = g * 512 + j0 + jj;

    const float4* wp = reinterpret_cast<const float4*>(Whh + (size_t)row * 512 + kc * 32);
    float4 w[8];
#pragma unroll
    for (int i = 0; i < 8; ++i) w[i] = wp[i];

    int ujj = tid >> 4, ub = tid & 15;          // valid when tid<64
    int ujg = j0 + ujj;
    if (tid < 64) c_sm[tid] = dc[ub * 512 + ujg];
    if (tid == 0) {
        unsigned v;
        asm volatile("ld.relaxed.gpu.global.u32 %0,[%1];"
                     : "=r"(v) : "l"(&g_bar[(17 + blockIdx.x) * 256]) : "memory");
        s_base = v;
    }
    __syncthreads();
    unsigned base = s_base;

    float gi = 0.f, gf = 0.f, gg_ = 0.f, go = 0.f;
    if (tid < 64) {
        const float* Gp = G + (size_t)ub * 2048 + ujg;    // t = 0
        gi = Gp[0]; gf = Gp[512]; gg_ = Gp[1024]; go = Gp[1536];
    }

    for (int t = 0; t < 48; ++t) {
        const float* h_in = (t == 0) ? dh : ((t & 1) ? hq : hp);
        float* h_out = (t & 1) ? hp : hq;
        const float4* hin4 = reinterpret_cast<const float4*>(h_in);
#pragma unroll
        for (int i = 0; i < 8; ++i) h4[tid + i * 256] = __ldcg(hin4 + tid + i * 256);
        __syncthreads();

        float acc[16];
#pragma unroll
        for (int i = 0; i < 16; ++i) acc[i] = 0.f;
#pragma unroll
        for (int b = 0; b < 16; ++b) {
            const float4* hb = &h4[b * 128 + kc * 8];
#pragma unroll
            for (int i = 0; i < 8; ++i) {
                float4 hv = hb[i];
                acc[b] += w[i].x * hv.x + w[i].y * hv.y + w[i].z * hv.z + w[i].w * hv.w;
            }
        }
        __syncthreads();                        // h4 reads done; safe to overlay red

        float4* redv = reinterpret_cast<float4*>(red);
        int rb = (kc * 16 + rid) * 4;
        redv[rb + 0] = make_float4(acc[0],  acc[1],  acc[2],  acc[3]);
        redv[rb + 1] = make_float4(acc[4],  acc[5],  acc[6],  acc[7]);
        redv[rb + 2] = make_float4(acc[8],  acc[9],  acc[10], acc[11]);
        redv[rb + 3] = make_float4(acc[12], acc[13], acc[14], acc[15]);
        __syncthreads();

        float s = 0.f;
#pragma unroll
        for (int q = 0; q < 16; ++q) s += red[q * 256 + tid];
        gsum[tid] = s;
        __syncthreads();

        if (tid < 64) {
            float ip = gsum[tid]       + gi;
            float fp = gsum[64 + tid]  + gf;
            float gp = gsum[128 + tid] + gg_;
            float op = gsum[192 + tid] + go;
            float c = sigm(fp) * c_sm[tid] + sigm(ip) * tanhf(gp);
            c_sm[tid] = c;
            float h = sigm(op) * tanhf(c);
            h_out[ub * 512 + ujg] = h;
            ds_out[(size_t)(t * 16 + ub) * 512 + ujg] = h;
        }
        if (t < 47) {
            if (tid < 64) {                      // prefetch next step's gates
                const float* Gp = G + (size_t)((t + 1) * 16 + ub) * 2048 + ujg;
                gi = Gp[0]; gf = Gp[512]; gg_ = Gp[1024]; go = Gp[1536];
            }
            gbar2(base + 1 + t);
        }
    }
}

// ======================= persistent encoder layer =======================
// 128 CTAs x 256 threads. dir = bx>>6; CTA owns 4 j of 256 (x 4 gates).
__global__ __launch_bounds__(256, 1) void enc_layer_k(
    const float* __restrict__ Whh,             // (2,1024,256)
    const float* __restrict__ G, float* __restrict__ xs_out,
    float* __restrict__ hp, float* __restrict__ hq,
    float* __restrict__ dh, float* __restrict__ dc) {
    __shared__ float4 h4[1024];                // 16KB
    __shared__ float red[4096];
    __shared__ float gsum[256];
    __shared__ float c_sm[64];
    __shared__ unsigned s_base;

    int tid = threadIdx.x;
    int kc = tid >> 4;
    int rid = tid & 15;
    int g = rid >> 2, jj = rid & 3;
    int dir = blockIdx.x >> 6;
    int j0 = (blockIdx.x & 63) * 4;
    int jg = j0 + jj;
    int row = g * 256 + jg;

    const float4* wp = reinterpret_cast<const float4*>(
        Whh + (size_t)dir * 1024 * 256 + (size_t)row * 256 + kc * 16);
    float4 w[4];
#pragma unroll
    for (int i = 0; i < 4; ++i) w[i] = wp[i];

    int ujj = tid >> 4, ub = tid & 15;          // valid when tid<64
    int ujg = j0 + ujj;
    if (tid < 64) c_sm[tid] = 0.f;
    if (tid == 0) {
        unsigned v;
        asm volatile("ld.relaxed.gpu.global.u32 %0,[%1];"
                     : "=r"(v) : "l"(&g_bar[(17 + blockIdx.x) * 256]) : "memory");
        s_base = v;
    }
    __syncthreads();
    unsigned base = s_base;

    float gi = 0.f, gf = 0.f, gg_ = 0.f, go = 0.f;
    if (tid < 64) {
        int tt0 = dir ? 47 : 0;
        const float* Gp = G + (size_t)(tt0 * 16 + ub) * 2048 + dir * 1024 + ujg;
        gi = Gp[0]; gf = Gp[256]; gg_ = Gp[512]; go = Gp[768];
    }

    for (int t = 0; t < 48; ++t) {
        int tt = dir ? (47 - t) : t;
        float* h_out = (t & 1) ? hp : hq;

        float s = 0.f;
        if (t > 0) {
            const float* h_in = (t & 1) ? hq : hp;
            const float4* hin4 = reinterpret_cast<const float4*>(h_in + dir * 4096);
#pragma unroll
            for (int i = 0; i < 4; ++i) h4[tid + i * 256] = __ldcg(hin4 + tid + i * 256);
            __syncthreads();

            float acc[16];
#pragma unroll
            for (int i = 0; i < 16; ++i) acc[i] = 0.f;
#pragma unroll
            for (int b = 0; b < 16; ++b) {
                const float4* hb = &h4[b * 64 + kc * 4];
#pragma unroll
                for (int i = 0; i < 4; ++i) {
                    float4 hv = hb[i];
                    acc[b] += w[i].x * hv.x + w[i].y * hv.y + w[i].z * hv.z + w[i].w * hv.w;
                }
            }
            float4* redv = reinterpret_cast<float4*>(red);
            int rb = (kc * 16 + rid) * 4;
            redv[rb + 0] = make_float4(acc[0],  acc[1],  acc[2],  acc[3]);
            redv[rb + 1] = make_float4(acc[4],  acc[5],  acc[6],  acc[7]);
            redv[rb + 2] = make_float4(acc[8],  acc[9],  acc[10], acc[11]);
            redv[rb + 3] = make_float4(acc[12], acc[13], acc[14], acc[15]);
            __syncthreads();
#pragma unroll
            for (int q = 0; q < 16; ++q) s += red[q * 256 + tid];
        }
        gsum[tid] = s;
        __syncthreads();

        if (tid < 64) {
            float ip = gsum[tid]       + gi;
            float fp = gsum[64 + tid]  + gf;
            float gp = gsum[128 + tid] + gg_;
            float op = gsum[192 + tid] + go;
            float c = sigm(fp) * c_sm[tid] + sigm(ip) * tanhf(gp);
            c_sm[tid] = c;
            float h = sigm(op) * tanhf(c);
            h_out[dir * 4096 + ub * 256 + ujg] = h;
            xs_out[(size_t)(tt * 16 + ub) * 512 + dir * 256 + ujg] = h;
            if (t == 47) {
                dh[ub * 512 + dir * 256 + ujg] = h;
                dc[ub * 512 + dir * 256 + ujg] = c;
            }
        }
        if (t < 47) {
            if (tid < 64) {                      // prefetch next step's gates
                int ttn = dir ? (47 - (t + 1)) : (t + 1);
                const float* Gp = G + (size_t)(ttn * 16 + ub) * 2048 + dir * 1024 + ujg;
                gi = Gp[0]; gf = Gp[256]; gg_ = Gp[512]; go = Gp[768];
            }
            gbar2(base + 1 + t);
        }
    }
}

// ---------------- launch sequence ----------------
extern "C" void kernel_launch(void* const* d_in, const int* in_sizes, int n_in,
                              void* d_out, int out_size) {
    const int*   x        = (const int*)d_in[0];
    const int*   y        = (const int*)d_in[1];
    const float* enc_emb  = (const float*)d_in[2];
    const float* enc_Wih  = (const float*)d_in[3];
    const float* enc_Whh  = (const float*)d_in[4];
    const float* enc_b    = (const float*)d_in[5];
    const float* dec_emb  = (const float*)d_in[6];
    const float* dec_Wih  = (const float*)d_in[7];
    const float* dec_Whh  = (const float*)d_in[8];
    const float* dec_b    = (const float*)d_in[9];
    const float* lin_W    = (const float*)d_in[10];
    const float* lin_b    = (const float*)d_in[11];
    float* out = (float*)d_out;

    float *act0, *act1, *G, *hp, *hq, *dh, *dc;
    cudaGetSymbolAddress((void**)&act0, g_act0);
    cudaGetSymbolAddress((void**)&act1, g_act1);
    cudaGetSymbolAddress((void**)&G,    g_G);
    cudaGetSymbolAddress((void**)&hp,   g_hping);
    cudaGetSymbolAddress((void**)&hq,   g_hpong);
    cudaGetSymbolAddress((void**)&dh,   g_dech0);
    cudaGetSymbolAddress((void**)&dc,   g_decc0);
    float* bufs[2] = {act0, act1};

    // ---- encoder ----
    embed_k<<<768, 128>>>(enc_emb, x, bufs[0]);
    int p = 0;
    for (int l = 0; l < NL; ++l) {
        gemm_k<<<dim3(32, 12), 256>>>(bufs[p], enc_Wih + (size_t)l * 1024 * 1024,
                                      enc_b + l * 2048, G,
                                      (size_t)2048, (size_t)32768, (size_t)1);
        enc_layer_k<<<128, 256>>>(enc_Whh + (size_t)l * 2 * 1024 * 256, G,
                                  bufs[1 - p], hp, hq,
                                  dh + l * 8192, dc + l * 8192);
        p ^= 1;
    }

    // ---- decoder ----
    embed_k<<<768, 128>>>(dec_emb, y, bufs[p]);
    for (int l = 0; l < NL; ++l) {
        gemm_k<<<dim3(32, 12), 256>>>(bufs[p], dec_Wih + (size_t)l * 2048 * 512,
                                      dec_b + l * 2048, G,
                                      (size_t)2048, (size_t)32768, (size_t)1);
        dec_layer_k<<<128, 256>>>(dec_Whh + (size_t)l * 2048 * 512, G,
                                  bufs[1 - p], hp, hq,
                                  dh + l * 8192, dc + l * 8192);
        p ^= 1;
    }

    // ---- final projection: out[b][v][t] ----
    gemm_k<<<dim3(500, 12), 256>>>(bufs[p], lin_W, lin_b, out,
                                   (size_t)VOUT * 48, (size_t)1, (size_t)48);
}

// round 8
// speedup vs baseline: 1.0765x; 1.0765x over previous
#include <cuda_runtime.h>
#include <math.h>

#define S 48
#define BATCH 16
#define HID 512
#define HDIR 256
#define NL 16
#define M_ROWS 768            // S*BATCH
#define VOUT 32000

// ---------------- device scratch (static, no allocation) ----------------
__device__ float g_act0[M_ROWS * HID];
__device__ float g_act1[M_ROWS * HID];
__device__ float g_G[M_ROWS * 2048];
__device__ float g_hping[8192];
__device__ float g_hpong[8192];
__device__ float g_dech0[NL * 8192];
__device__ float g_decc0[NL * 8192];
// sync words, each on its own 1KB line (stride 256 u32):
// enc dom d (d=0,1): group cnts @ [d*4096 + g*256] g<8, root @ [d*4096+2048], gen @ [d*4096+2304]
// dec: group cnts @ [8192 + g*256] g<16, root @ [8192+4096], gen @ [8192+4352]
__device__ unsigned g_syn[16384];

// ---------------- two-level grid barrier, spin-then-sleep poll ----------------
__device__ __forceinline__ void gbar(unsigned* gcnt, unsigned* rcnt, unsigned* gen,
                                     unsigned gsz, unsigned nroot, unsigned tgt) {
    __syncthreads();
    if (threadIdx.x == 0) {
        __threadfence();                      // drain this CTA's h/ds stores
        unsigned old;
        asm volatile("atom.release.gpu.global.add.u32 %0,[%1],%2;"
                     : "=r"(old) : "l"(gcnt), "r"(1u) : "memory");
        if (old == gsz - 1u) {
            asm volatile("st.relaxed.gpu.global.u32 [%0],%1;" :: "l"(gcnt), "r"(0u) : "memory");
            asm volatile("atom.release.gpu.global.add.u32 %0,[%1],%2;"
                         : "=r"(old) : "l"(rcnt), "r"(1u) : "memory");
            if (old == nroot - 1u) {
                asm volatile("st.relaxed.gpu.global.u32 [%0],%1;" :: "l"(rcnt), "r"(0u) : "memory");
                __threadfence();
                asm volatile("st.relaxed.gpu.global.u32 [%0],%1;" :: "l"(gen), "r"(tgt) : "memory");
            }
        }
        unsigned v; int sp = 0;
        do {
            asm volatile("ld.relaxed.gpu.global.u32 %0,[%1];" : "=r"(v) : "l"(gen) : "memory");
            if (++sp > 384) __nanosleep(64);
        } while ((int)(v - tgt) < 0);
        __threadfence();
    }
    __syncthreads();
}

// ---------------- embedding gather ----------------
__global__ void embed_k(const float* __restrict__ emb, const int* __restrict__ ids,
                        float* __restrict__ out) {
    int tb = blockIdx.x;            // t*16+b
    int t = tb >> 4, b = tb & 15;
    int id = ids[b * S + t];
    const float4* src = reinterpret_cast<const float4*>(emb) + (size_t)id * (HID / 4);
    float4* dst = reinterpret_cast<float4*>(out) + (size_t)tb * (HID / 4);
    dst[threadIdx.x] = src[threadIdx.x];
}

// -------- C[m][n] = A[m][:512] . W[n][:512] + bias[n], M=768, K=512 ---------
// 64x64 tile, double-buffered smem, one sync per K-iter (prefetch hides LDG).
__global__ __launch_bounds__(256) void gemm_k(
    const float* __restrict__ A, const float* __restrict__ W,
    const float* __restrict__ bias, float* __restrict__ C,
    size_t sB, size_t sT, size_t sN) {
    __shared__ float As[2][16 * 68];
    __shared__ float Ws[2][16 * 68];
    int tid = threadIdx.x;
    int tx = tid & 15, ty = tid >> 4;
    int n0 = blockIdx.x * 64, m0 = blockIdx.y * 64;
    int r = tid >> 2, kq = (tid & 3) * 4;

    const float* Arow = A + (size_t)(m0 + r) * 512 + kq;
    const float* Wrow = W + (size_t)(n0 + r) * 512 + kq;

    float4 a = *reinterpret_cast<const float4*>(Arow);
    float4 w = *reinterpret_cast<const float4*>(Wrow);
    As[0][(kq + 0) * 68 + r] = a.x; As[0][(kq + 1) * 68 + r] = a.y;
    As[0][(kq + 2) * 68 + r] = a.z; As[0][(kq + 3) * 68 + r] = a.w;
    Ws[0][(kq + 0) * 68 + r] = w.x; Ws[0][(kq + 1) * 68 + r] = w.y;
    Ws[0][(kq + 2) * 68 + r] = w.z; Ws[0][(kq + 3) * 68 + r] = w.w;
    __syncthreads();

    float acc[16];
#pragma unroll
    for (int i = 0; i < 16; ++i) acc[i] = 0.f;

    for (int k0 = 0; k0 < 512; k0 += 16) {
        int cur = (k0 >> 4) & 1;
        if (k0 + 16 < 512) {                      // prefetch next tile (hidden by compute)
            a = *reinterpret_cast<const float4*>(Arow + k0 + 16);
            w = *reinterpret_cast<const float4*>(Wrow + k0 + 16);
        }
#pragma unroll
        for (int kk = 0; kk < 16; ++kk) {
            float4 av = *reinterpret_cast<const float4*>(&As[cur][kk * 68 + ty * 4]);
            float4 wv = *reinterpret_cast<const float4*>(&Ws[cur][kk * 68 + tx * 4]);
            acc[0]  += av.x * wv.x; acc[1]  += av.x * wv.y; acc[2]  += av.x * wv.z; acc[3]  += av.x * wv.w;
            acc[4]  += av.y * wv.x; acc[5]  += av.y * wv.y; acc[6]  += av.y * wv.z; acc[7]  += av.y * wv.w;
            acc[8]  += av.z * wv.x; acc[9]  += av.z * wv.y; acc[10] += av.z * wv.z; acc[11] += av.z * wv.w;
            acc[12] += av.w * wv.x; acc[13] += av.w * wv.y; acc[14] += av.w * wv.z; acc[15] += av.w * wv.w;
        }
        if (k0 + 16 < 512) {
            int nxt = cur ^ 1;
            As[nxt][(kq + 0) * 68 + r] = a.x; As[nxt][(kq + 1) * 68 + r] = a.y;
            As[nxt][(kq + 2) * 68 + r] = a.z; As[nxt][(kq + 3) * 68 + r] = a.w;
            Ws[nxt][(kq + 0) * 68 + r] = w.x; Ws[nxt][(kq + 1) * 68 + r] = w.y;
            Ws[nxt][(kq + 2) * 68 + r] = w.z; Ws[nxt][(kq + 3) * 68 + r] = w.w;
        }
        __syncthreads();
    }
#pragma unroll
    for (int i = 0; i < 4; ++i) {
        int m = m0 + ty * 4 + i;
        int b = m & 15, t = m >> 4;
#pragma unroll
        for (int jx = 0; jx < 4; ++jx) {
            int n = n0 + tx * 4 + jx;
            C[(size_t)b * sB + (size_t)t * sT + (size_t)n * sN] = acc[i * 4 + jx] + bias[n];
        }
    }
}

__device__ __forceinline__ float sigm(float x) { return 1.f / (1.f + expf(-x)); }

// ======================= persistent encoder layer (R3 128-thr body) ========
// grid 128: bx>>6 = dir (independent sync domain), bx&63 = j-block (4 j).
__global__ __launch_bounds__(128, 1) void enc_layer_k(
    const float* __restrict__ Whh,             // (2,1024,256)
    const float* __restrict__ G, float* __restrict__ xs_out,
    float* __restrict__ hp, float* __restrict__ hq,
    float* __restrict__ dh, float* __restrict__ dc) {
    __shared__ float4 sm4[2112];
    __shared__ float redout[256];
    __shared__ float c_sm[64];
    __shared__ unsigned s_base;
    float* sm = (float*)sm4;
    int tid = threadIdx.x;
    int ty = tid >> 5, kc = tid & 31;
    int dir = blockIdx.x >> 6;
    int jb = blockIdx.x & 63;
    int j0 = jb * 4;
    int j = j0 + ty;

    unsigned* gcnt = &g_syn[dir * 4096 + ((blockIdx.x & 63) >> 3) * 256];
    unsigned* rcnt = &g_syn[dir * 4096 + 2048];
    unsigned* gen  = &g_syn[dir * 4096 + 2304];

    // recurrent weights in registers across all 48 steps
    const float4* w4 = reinterpret_cast<const float4*>(Whh + (size_t)dir * 1024 * 256);
    float4 wr[2][4];
#pragma unroll
    for (int it = 0; it < 2; ++it) {
        int k4 = it * 32 + kc;
        wr[it][0] = w4[(size_t)(0 * 256 + j) * 64 + k4];
        wr[it][1] = w4[(size_t)(1 * 256 + j) * 64 + k4];
        wr[it][2] = w4[(size_t)(2 * 256 + j) * 64 + k4];
        wr[it][3] = w4[(size_t)(3 * 256 + j) * 64 + k4];
    }
    if (tid < 64) c_sm[tid] = 0.f;
    if (tid == 0) {
        unsigned v;
        asm volatile("ld.relaxed.gpu.global.u32 %0,[%1];" : "=r"(v) : "l"(gen) : "memory");
        s_base = v;
    }
    __syncthreads();
    unsigned base = s_base;

    int ujj = tid >> 4, ub = tid & 15;          // valid for tid<64
    int ujg = j0 + ujj;
    float gi = 0.f, gf = 0.f, gg_ = 0.f, go = 0.f;
    if (tid < 64) {
        int tt0 = dir ? 47 : 0;
        const float* Gp = G + (size_t)(tt0 * 16 + ub) * 2048 + dir * 1024 + ujg;
        gi = Gp[0]; gf = Gp[256]; gg_ = Gp[512]; go = Gp[768];
    }

    for (int t = 0; t < 48; ++t) {
        int tt = dir ? (47 - t) : t;
        float* h_out = (t & 1) ? hp : hq;

        if (t > 0) {                             // t=0: h=0 -> matvec is zero
            const float* h_in = (t & 1) ? hq : hp;
            const float4* hin4 = reinterpret_cast<const float4*>(h_in + dir * 4096);
#pragma unroll
            for (int i = 0; i < 8; ++i) sm4[tid + i * 128] = hin4[tid + i * 128];
            __syncthreads();

            float acc[64];
#pragma unroll
            for (int i = 0; i < 64; ++i) acc[i] = 0.f;
#pragma unroll
            for (int it = 0; it < 2; ++it) {
                int k4 = it * 32 + kc;
#pragma unroll
                for (int b = 0; b < 16; ++b) {
                    float4 hv = sm4[b * 64 + k4];
                    acc[0 * 16 + b] += wr[it][0].x * hv.x + wr[it][0].y * hv.y + wr[it][0].z * hv.z + wr[it][0].w * hv.w;
                    acc[1 * 16 + b] += wr[it][1].x * hv.x + wr[it][1].y * hv.y + wr[it][1].z * hv.z + wr[it][1].w * hv.w;
                    acc[2 * 16 + b] += wr[it][2].x * hv.x + wr[it][2].y * hv.y + wr[it][2].z * hv.z + wr[it][2].w * hv.w;
                    acc[3 * 16 + b] += wr[it][3].x * hv.x + wr[it][3].y * hv.y + wr[it][3].z * hv.z + wr[it][3].w * hv.w;
                }
            }
            __syncthreads();
#pragma unroll
            for (int g = 0; g < 4; ++g)
#pragma unroll
                for (int b = 0; b < 16; ++b)
                    sm[((ty * 4 + g) * 16 + b) * 33 + kc] = acc[g * 16 + b];
            __syncthreads();
#pragma unroll
            for (int rr = 0; rr < 2; ++rr) {
                int o = tid + rr * 128;
                float s = 0.f;
#pragma unroll
                for (int q = 0; q < 32; ++q) s += sm[o * 33 + q];
                redout[o] = s;
            }
        } else {
#pragma unroll
            for (int rr = 0; rr < 2; ++rr) redout[tid + rr * 128] = 0.f;
        }
        __syncthreads();

        if (tid < 64) {
            float ip = redout[(ujj * 4 + 0) * 16 + ub] + gi;
            float fp = redout[(ujj * 4 + 1) * 16 + ub] + gf;
            float gp = redout[(ujj * 4 + 2) * 16 + ub] + gg_;
            float op = redout[(ujj * 4 + 3) * 16 + ub] + go;
            float c = sigm(fp) * c_sm[tid] + sigm(ip) * tanhf(gp);
            c_sm[tid] = c;
            float h = sigm(op) * tanhf(c);
            h_out[dir * 4096 + ub * 256 + ujg] = h;
            xs_out[(size_t)(tt * 16 + ub) * 512 + dir * 256 + ujg] = h;
            if (t == 47) {
                dh[ub * 512 + dir * 256 + ujg] = h;
                dc[ub * 512 + dir * 256 + ujg] = c;
            }
        }
        if (t < 47) {
            if (tid < 64) {                      // prefetch next step's gates
                int ttn = dir ? (47 - (t + 1)) : (t + 1);
                const float* Gp = G + (size_t)(ttn * 16 + ub) * 2048 + dir * 1024 + ujg;
                gi = Gp[0]; gf = Gp[256]; gg_ = Gp[512]; go = Gp[768];
            }
            gbar(gcnt, rcnt, gen, 8u, 8u, base + 1 + t);
        }
    }
}

// ======================= persistent decoder layer (R3 128-thr body) ========
// grid 128 (4 j each), block 128 = 4 j-lanes x 32 k-chunks.
__global__ __launch_bounds__(128, 1) void dec_layer_k(
    const float* __restrict__ Whh,             // (2048,512)
    const float* __restrict__ G, float* __restrict__ ds_out,
    float* __restrict__ hp, float* __restrict__ hq,
    const float* __restrict__ dh, const float* __restrict__ dc) {
    __shared__ float4 sm4[2112];
    __shared__ float redout[256];
    __shared__ float c_sm[64];
    __shared__ unsigned s_base;
    float* sm = (float*)sm4;
    int tid = threadIdx.x;
    int ty = tid >> 5;
    int kc = tid & 31;
    int j0 = blockIdx.x * 4;
    int j = j0 + ty;

    unsigned* gcnt = &g_syn[8192 + (blockIdx.x >> 3) * 256];
    unsigned* rcnt = &g_syn[8192 + 4096];
    unsigned* gen  = &g_syn[8192 + 4352];

    const float4* w4 = reinterpret_cast<const float4*>(Whh);
    float4 wr[4][4];
#pragma unroll
    for (int it = 0; it < 4; ++it) {
        int k4 = it * 32 + kc;
        wr[it][0] = w4[(size_t)(0 * 512 + j) * 128 + k4];
        wr[it][1] = w4[(size_t)(1 * 512 + j) * 128 + k4];
        wr[it][2] = w4[(size_t)(2 * 512 + j) * 128 + k4];
        wr[it][3] = w4[(size_t)(3 * 512 + j) * 128 + k4];
    }
    int ujj = tid >> 4, ub = tid & 15;          // valid for tid<64
    int ujg = j0 + ujj;
    if (tid < 64) c_sm[tid] = dc[ub * 512 + ujg];
    if (tid == 0) {
        unsigned v;
        asm volatile("ld.relaxed.gpu.global.u32 %0,[%1];" : "=r"(v) : "l"(gen) : "memory");
        s_base = v;
    }
    __syncthreads();
    unsigned base = s_base;

    float gi = 0.f, gf = 0.f, gg_ = 0.f, go = 0.f;
    if (tid < 64) {
        const float* Gp = G + (size_t)ub * 2048 + ujg;    // t=0
        gi = Gp[0]; gf = Gp[512]; gg_ = Gp[1024]; go = Gp[1536];
    }

    for (int t = 0; t < 48; ++t) {
        const float* h_in = (t == 0) ? dh : ((t & 1) ? hq : hp);
        float* h_out = (t & 1) ? hp : hq;
        const float4* hin4 = reinterpret_cast<const float4*>(h_in);
#pragma unroll
        for (int i = 0; i < 16; ++i) sm4[tid + i * 128] = hin4[tid + i * 128];
        __syncthreads();

        float acc[64];
#pragma unroll
        for (int i = 0; i < 64; ++i) acc[i] = 0.f;
#pragma unroll
        for (int it = 0; it < 4; ++it) {
            int k4 = it * 32 + kc;
#pragma unroll
            for (int b = 0; b < 16; ++b) {
                float4 hv = sm4[b * 128 + k4];
                acc[0 * 16 + b] += wr[it][0].x * hv.x + wr[it][0].y * hv.y + wr[it][0].z * hv.z + wr[it][0].w * hv.w;
                acc[1 * 16 + b] += wr[it][1].x * hv.x + wr[it][1].y * hv.y + wr[it][1].z * hv.z + wr[it][1].w * hv.w;
                acc[2 * 16 + b] += wr[it][2].x * hv.x + wr[it][2].y * hv.y + wr[it][2].z * hv.z + wr[it][2].w * hv.w;
                acc[3 * 16 + b] += wr[it][3].x * hv.x + wr[it][3].y * hv.y + wr[it][3].z * hv.z + wr[it][3].w * hv.w;
            }
        }
        __syncthreads();
#pragma unroll
        for (int g = 0; g < 4; ++g)
#pragma unroll
            for (int b = 0; b < 16; ++b)
                sm[((ty * 4 + g) * 16 + b) * 33 + kc] = acc[g * 16 + b];
        __syncthreads();
#pragma unroll
        for (int rr = 0; rr < 2; ++rr) {
            int o = tid + rr * 128;
            float s = 0.f;
#pragma unroll
            for (int q = 0; q < 32; ++q) s += sm[o * 33 + q];
            redout[o] = s;
        }
        __syncthreads();

        if (tid < 64) {
            float ip = redout[(ujj * 4 + 0) * 16 + ub] + gi;
            float fp = redout[(ujj * 4 + 1) * 16 + ub] + gf;
            float gp = redout[(ujj * 4 + 2) * 16 + ub] + gg_;
            float op = redout[(ujj * 4 + 3) * 16 + ub] + go;
            float c = sigm(fp) * c_sm[tid] + sigm(ip) * tanhf(gp);
            c_sm[tid] = c;
            float h = sigm(op) * tanhf(c);
            h_out[ub * 512 + ujg] = h;
            ds_out[(size_t)(t * 16 + ub) * 512 + ujg] = h;
        }
        if (t < 47) {
            if (tid < 64) {                      // prefetch next step's gates
                const float* Gp = G + (size_t)((t + 1) * 16 + ub) * 2048 + ujg;
                gi = Gp[0]; gf = Gp[512]; gg_ = Gp[1024]; go = Gp[1536];
            }
            gbar(gcnt, rcnt, gen, 8u, 16u, base + 1 + t);
        }
    }
}

// ---------------- launch sequence ----------------
extern "C" void kernel_launch(void* const* d_in, const int* in_sizes, int n_in,
                              void* d_out, int out_size) {
    const int*   x        = (const int*)d_in[0];
    const int*   y        = (const int*)d_in[1];
    const float* enc_emb  = (const float*)d_in[2];
    const float* enc_Wih  = (const float*)d_in[3];
    const float* enc_Whh  = (const float*)d_in[4];
    const float* enc_b    = (const float*)d_in[5];
    const float* dec_emb  = (const float*)d_in[6];
    const float* dec_Wih  = (const float*)d_in[7];
    const float* dec_Whh  = (const float*)d_in[8];
    const float* dec_b    = (const float*)d_in[9];
    const float* lin_W    = (const float*)d_in[10];
    const float* lin_b    = (const float*)d_in[11];
    float* out = (float*)d_out;

    float *act0, *act1, *G, *hp, *hq, *dh, *dc;
    cudaGetSymbolAddress((void**)&act0, g_act0);
    cudaGetSymbolAddress((void**)&act1, g_act1);
    cudaGetSymbolAddress((void**)&G,    g_G);
    cudaGetSymbolAddress((void**)&hp,   g_hping);
    cudaGetSymbolAddress((void**)&hq,   g_hpong);
    cudaGetSymbolAddress((void**)&dh,   g_dech0);
    cudaGetSymbolAddress((void**)&dc,   g_decc0);
    float* bufs[2] = {act0, act1};

    // ---- encoder ----
    embed_k<<<768, 128>>>(enc_emb, x, bufs[0]);
    int p = 0;
    for (int l = 0; l < NL; ++l) {
        gemm_k<<<dim3(32, 12), 256>>>(bufs[p], enc_Wih + (size_t)l * 1024 * 1024,
                                      enc_b + l * 2048, G,
                                      (size_t)2048, (size_t)32768, (size_t)1);
        enc_layer_k<<<128, 128>>>(enc_Whh + (size_t)l * 2 * 1024 * 256, G,
                                  bufs[1 - p], hp, hq,
                                  dh + l * 8192, dc + l * 8192);
        p ^= 1;
    }

    // ---- decoder ----
    embed_k<<<768, 128>>>(dec_emb, y, bufs[p]);
    for (int l = 0; l < NL; ++l) {
        gemm_k<<<dim3(32, 12), 256>>>(bufs[p], dec_Wih + (size_t)l * 2048 * 512,
                                      dec_b + l * 2048, G,
                                      (size_t)2048, (size_t)32768, (size_t)1);
        dec_layer_k<<<128, 128>>>(dec_Whh + (size_t)l * 2048 * 512, G,
                                  bufs[1 - p], hp, hq,
                                  dh + l * 8192, dc + l * 8192);
        p ^= 1;
    }

    // ---- final projection: out[b][v][t] ----
    gemm_k<<<dim3(500, 12), 256>>>(bufs[p], lin_W, lin_b, out,
                                   (size_t)VOUT * 48, (size_t)1, (size_t)48);
}

// round 9
// speedup vs baseline: 1.1405x; 1.0594x over previous
#include <cuda_runtime.h>
#include <math.h>

#define S 48
#define BATCH 16
#define HID 512
#define HDIR 256
#define NL 16
#define M_ROWS 768            // S*BATCH
#define VOUT 32000

// ---------------- device scratch (static, no allocation) ----------------
__device__ float g_act0[M_ROWS * HID];
__device__ float g_act1[M_ROWS * HID];
__device__ float g_G[M_ROWS * 2048];
__device__ float g_hping[8192];
__device__ float g_hpong[8192];
__device__ float g_dech0[NL * 8192];
__device__ float g_decc0[NL * 8192];
__device__ unsigned g_cnt = 0;
__device__ unsigned g_gen = 0;

// ---------------- R3's measured-best grid barrier (verbatim protocol) ----------------
__device__ __forceinline__ void grid_bar(unsigned tgt, unsigned nb) {
    __syncthreads();
    if (threadIdx.x == 0) {
        __threadfence();
        unsigned old = atomicAdd(&g_cnt, 1u);
        if (old == nb - 1u) {
            atomicExch(&g_cnt, 0u);
            __threadfence();
            atomicExch(&g_gen, tgt);
        } else {
            while (*(volatile unsigned*)&g_gen != tgt) { __nanosleep(32); }
        }
        __threadfence();
    }
    __syncthreads();
}

// ---------------- embedding gather ----------------
__global__ void embed_k(const float* __restrict__ emb, const int* __restrict__ ids,
                        float* __restrict__ out) {
    int tb = blockIdx.x;            // t*16+b
    int t = tb >> 4, b = tb & 15;
    int id = ids[b * S + t];
    const float4* src = reinterpret_cast<const float4*>(emb) + (size_t)id * (HID / 4);
    float4* dst = reinterpret_cast<float4*>(out) + (size_t)tb * (HID / 4);
    dst[threadIdx.x] = src[threadIdx.x];
}

// ---------------- 3xTF32 tensor-core GEMM ----------------
// C[m][n] = A[m][:512] . W[n][:512] + bias[n], m = t*16+b, out addr b*sB+t*sT+n*sN.
// CTA 128 thr / 4 warps, 64x64 tile; K chunks of 16 staged in smem (hi/lo tf32,
// k-permuted so (k,k+4) pairs are adjacent -> LDS.64 fragment reads).
__device__ __forceinline__ unsigned f2tf(float v) {
    unsigned r; asm("cvt.rna.tf32.f32 %0, %1;" : "=r"(r) : "f"(v)); return r;
}
#define MMA_TF32(c, a0, a1, a2, a3, b0, b1)                                          \
    asm volatile("mma.sync.aligned.m16n8k8.row.col.f32.tf32.tf32.f32 "               \
                 "{%0,%1,%2,%3},{%4,%5,%6,%7},{%8,%9},{%0,%1,%2,%3};"                \
                 : "+f"(c[0]), "+f"(c[1]), "+f"(c[2]), "+f"(c[3])                    \
                 : "r"(a0), "r"(a1), "r"(a2), "r"(a3), "r"(b0), "r"(b1))

__global__ __launch_bounds__(128) void gemm_tc(
    const float* __restrict__ A, const float* __restrict__ W,
    const float* __restrict__ bias, float* __restrict__ C,
    size_t sB, size_t sT, size_t sN) {
    __shared__ unsigned sAhi[64 * 20], sAlo[64 * 20];
    __shared__ unsigned sWhi[64 * 20], sWlo[64 * 20];

    int tid = threadIdx.x;
    int w = tid >> 5, lane = tid & 31;
    int g = lane >> 2, ctid = lane & 3;
    int n0 = blockIdx.x * 64, m0 = blockIdx.y * 64;

    int r = tid >> 1;                 // 0..63: tile row this thread loads
    int kh = (tid & 1) * 8;           // k-half within chunk (also = sub*8)
    const float* Ap = A + (size_t)(m0 + r) * 512 + kh;
    const float* Wp = W + (size_t)(n0 + r) * 512 + kh;

    float4 ra0 = *reinterpret_cast<const float4*>(Ap);
    float4 ra1 = *reinterpret_cast<const float4*>(Ap + 4);
    float4 rw0 = *reinterpret_cast<const float4*>(Wp);
    float4 rw1 = *reinterpret_cast<const float4*>(Wp + 4);

    float acc[8][4];
#pragma unroll
    for (int i = 0; i < 8; ++i)
#pragma unroll
        for (int q = 0; q < 4; ++q) acc[i][q] = 0.f;

    int mrow = w * 16 + g;

    for (int k0 = 0; k0 < 512; k0 += 16) {
        __syncthreads();              // previous chunk's readers done
        {   // store hi/lo (k-permuted: pos = kh + (j&3)*2 + (j>>2))
            float av[8] = {ra0.x, ra0.y, ra0.z, ra0.w, ra1.x, ra1.y, ra1.z, ra1.w};
            float wv[8] = {rw0.x, rw0.y, rw0.z, rw0.w, rw1.x, rw1.y, rw1.z, rw1.w};
#pragma unroll
            for (int j = 0; j < 8; ++j) {
                int pos = r * 20 + kh + (j & 3) * 2 + (j >> 2);
                unsigned ah = f2tf(av[j]);
                sAhi[pos] = ah;
                sAlo[pos] = f2tf(av[j] - __uint_as_float(ah));
                unsigned wh = f2tf(wv[j]);
                sWhi[pos] = wh;
                sWlo[pos] = f2tf(wv[j] - __uint_as_float(wh));
            }
        }
        __syncthreads();
        if (k0 + 16 < 512) {          // prefetch next chunk (hidden by mma below)
            ra0 = *reinterpret_cast<const float4*>(Ap + k0 + 16);
            ra1 = *reinterpret_cast<const float4*>(Ap + k0 + 20);
            rw0 = *reinterpret_cast<const float4*>(Wp + k0 + 16);
            rw1 = *reinterpret_cast<const float4*>(Wp + k0 + 20);
        }
#pragma unroll
        for (int sub = 0; sub < 2; ++sub) {
            uint2 aH0 = *reinterpret_cast<const uint2*>(&sAhi[mrow * 20 + sub * 8 + ctid * 2]);
            uint2 aH1 = *reinterpret_cast<const uint2*>(&sAhi[(mrow + 8) * 20 + sub * 8 + ctid * 2]);
            uint2 aL0 = *reinterpret_cast<const uint2*>(&sAlo[mrow * 20 + sub * 8 + ctid * 2]);
            uint2 aL1 = *reinterpret_cast<const uint2*>(&sAlo[(mrow + 8) * 20 + sub * 8 + ctid * 2]);
#pragma unroll
            for (int nb = 0; nb < 8; ++nb) {
                uint2 bH = *reinterpret_cast<const uint2*>(&sWhi[(nb * 8 + g) * 20 + sub * 8 + ctid * 2]);
                uint2 bL = *reinterpret_cast<const uint2*>(&sWlo[(nb * 8 + g) * 20 + sub * 8 + ctid * 2]);
                MMA_TF32(acc[nb], aH0.x, aH1.x, aH0.y, aH1.y, bH.x, bH.y);
                MMA_TF32(acc[nb], aH0.x, aH1.x, aH0.y, aH1.y, bL.x, bL.y);
                MMA_TF32(acc[nb], aL0.x, aL1.x, aL0.y, aL1.y, bH.x, bH.y);
            }
        }
    }

    int m1 = m0 + w * 16 + g;
    int m2 = m1 + 8;
    int b1 = m1 & 15, t1 = m1 >> 4;
    int b2 = m2 & 15, t2 = m2 >> 4;
#pragma unroll
    for (int nb = 0; nb < 8; ++nb) {
        int n = n0 + nb * 8 + ctid * 2;
        float bs0 = bias[n], bs1 = bias[n + 1];
        C[(size_t)b1 * sB + (size_t)t1 * sT + (size_t)n * sN]       = acc[nb][0] + bs0;
        C[(size_t)b1 * sB + (size_t)t1 * sT + (size_t)(n + 1) * sN] = acc[nb][1] + bs1;
        C[(size_t)b2 * sB + (size_t)t2 * sT + (size_t)n * sN]       = acc[nb][2] + bs0;
        C[(size_t)b2 * sB + (size_t)t2 * sT + (size_t)(n + 1) * sN] = acc[nb][3] + bs1;
    }
}

__device__ __forceinline__ float sigm(float x) { return 1.f / (1.f + expf(-x)); }

// ======================= persistent encoder layer ========
// grid 128: bx>>6 = dir, bx&63 = j-block (4 j). block 128 = 4 j x 32 k-chunks.
__global__ __launch_bounds__(128, 1) void enc_layer_k(
    const float* __restrict__ Whh,             // (2,1024,256)
    const float* __restrict__ G, float* __restrict__ xs_out,
    float* __restrict__ hp, float* __restrict__ hq,
    float* __restrict__ dh, float* __restrict__ dc) {
    __shared__ float4 sm4[2112];
    __shared__ float redout[256];
    __shared__ float c_sm[64];
    __shared__ unsigned s_base;
    float* sm = (float*)sm4;
    int tid = threadIdx.x;
    int ty = tid >> 5, kc = tid & 31;
    int dir = blockIdx.x >> 6;
    int jb = blockIdx.x & 63;
    int j0 = jb * 4;
    int j = j0 + ty;

    const float4* w4 = reinterpret_cast<const float4*>(Whh + (size_t)dir * 1024 * 256);
    float4 wr[2][4];
#pragma unroll
    for (int it = 0; it < 2; ++it) {
        int k4 = it * 32 + kc;
        wr[it][0] = w4[(size_t)(0 * 256 + j) * 64 + k4];
        wr[it][1] = w4[(size_t)(1 * 256 + j) * 64 + k4];
        wr[it][2] = w4[(size_t)(2 * 256 + j) * 64 + k4];
        wr[it][3] = w4[(size_t)(3 * 256 + j) * 64 + k4];
    }
    if (tid < 64) c_sm[tid] = 0.f;
    if (tid == 0) s_base = *(volatile unsigned*)&g_gen;
    __syncthreads();
    unsigned base = s_base;

    int ujj = tid >> 4, ub = tid & 15;          // valid for tid<64
    int ujg = j0 + ujj;
    float gi = 0.f, gf = 0.f, gg_ = 0.f, go = 0.f;
    if (tid < 64) {
        int tt0 = dir ? 47 : 0;
        const float* Gp = G + (size_t)(tt0 * 16 + ub) * 2048 + dir * 1024 + ujg;
        gi = Gp[0]; gf = Gp[256]; gg_ = Gp[512]; go = Gp[768];
    }

    for (int t = 0; t < 48; ++t) {
        int tt = dir ? (47 - t) : t;
        float* h_out = (t & 1) ? hp : hq;

        if (t > 0) {                             // t=0: h=0 -> matvec is zero
            const float* h_in = (t & 1) ? hq : hp;
            const float4* hin4 = reinterpret_cast<const float4*>(h_in + dir * 4096);
#pragma unroll
            for (int i = 0; i < 8; ++i) sm4[tid + i * 128] = hin4[tid + i * 128];
            __syncthreads();

            float acc[64];
#pragma unroll
            for (int i = 0; i < 64; ++i) acc[i] = 0.f;
#pragma unroll
            for (int it = 0; it < 2; ++it) {
                int k4 = it * 32 + kc;
#pragma unroll
                for (int b = 0; b < 16; ++b) {
                    float4 hv = sm4[b * 64 + k4];
                    acc[0 * 16 + b] += wr[it][0].x * hv.x + wr[it][0].y * hv.y + wr[it][0].z * hv.z + wr[it][0].w * hv.w;
                    acc[1 * 16 + b] += wr[it][1].x * hv.x + wr[it][1].y * hv.y + wr[it][1].z * hv.z + wr[it][1].w * hv.w;
                    acc[2 * 16 + b] += wr[it][2].x * hv.x + wr[it][2].y * hv.y + wr[it][2].z * hv.z + wr[it][2].w * hv.w;
                    acc[3 * 16 + b] += wr[it][3].x * hv.x + wr[it][3].y * hv.y + wr[it][3].z * hv.z + wr[it][3].w * hv.w;
                }
            }
            __syncthreads();
#pragma unroll
            for (int gg = 0; gg < 4; ++gg)
#pragma unroll
                for (int b = 0; b < 16; ++b)
                    sm[((ty * 4 + gg) * 16 + b) * 33 + kc] = acc[gg * 16 + b];
            __syncthreads();
#pragma unroll
            for (int rr = 0; rr < 2; ++rr) {
                int o = tid + rr * 128;
                float s = 0.f;
#pragma unroll
                for (int q = 0; q < 32; ++q) s += sm[o * 33 + q];
                redout[o] = s;
            }
        } else {
#pragma unroll
            for (int rr = 0; rr < 2; ++rr) redout[tid + rr * 128] = 0.f;
        }
        __syncthreads();

        if (tid < 64) {
            float ip = redout[(ujj * 4 + 0) * 16 + ub] + gi;
            float fp = redout[(ujj * 4 + 1) * 16 + ub] + gf;
            float gp = redout[(ujj * 4 + 2) * 16 + ub] + gg_;
            float op = redout[(ujj * 4 + 3) * 16 + ub] + go;
            float c = sigm(fp) * c_sm[tid] + sigm(ip) * tanhf(gp);
            c_sm[tid] = c;
            float h = sigm(op) * tanhf(c);
            h_out[dir * 4096 + ub * 256 + ujg] = h;
            xs_out[(size_t)(tt * 16 + ub) * 512 + dir * 256 + ujg] = h;
            if (t == 47) {
                dh[ub * 512 + dir * 256 + ujg] = h;
                dc[ub * 512 + dir * 256 + ujg] = c;
            }
        }
        if (t < 47) {
            if (tid < 64) {                      // prefetch next step's gates
                int ttn = dir ? (47 - (t + 1)) : (t + 1);
                const float* Gp = G + (size_t)(ttn * 16 + ub) * 2048 + dir * 1024 + ujg;
                gi = Gp[0]; gf = Gp[256]; gg_ = Gp[512]; go = Gp[768];
            }
            grid_bar(base + 1 + t, 128u);
        }
    }
}

// ======================= persistent decoder layer ========
__global__ __launch_bounds__(128, 1) void dec_layer_k(
    const float* __restrict__ Whh,             // (2048,512)
    const float* __restrict__ G, float* __restrict__ ds_out,
    float* __restrict__ hp, float* __restrict__ hq,
    const float* __restrict__ dh, const float* __restrict__ dc) {
    __shared__ float4 sm4[2112];
    __shared__ float redout[256];
    __shared__ float c_sm[64];
    __shared__ unsigned s_base;
    float* sm = (float*)sm4;
    int tid = threadIdx.x;
    int ty = tid >> 5;
    int kc = tid & 31;
    int j0 = blockIdx.x * 4;
    int j = j0 + ty;

    const float4* w4 = reinterpret_cast<const float4*>(Whh);
    float4 wr[4][4];
#pragma unroll
    for (int it = 0; it < 4; ++it) {
        int k4 = it * 32 + kc;
        wr[it][0] = w4[(size_t)(0 * 512 + j) * 128 + k4];
        wr[it][1] = w4[(size_t)(1 * 512 + j) * 128 + k4];
        wr[it][2] = w4[(size_t)(2 * 512 + j) * 128 + k4];
        wr[it][3] = w4[(size_t)(3 * 512 + j) * 128 + k4];
    }
    int ujj = tid >> 4, ub = tid & 15;          // valid for tid<64
    int ujg = j0 + ujj;
    if (tid < 64) c_sm[tid] = dc[ub * 512 + ujg];
    if (tid == 0) s_base = *(volatile unsigned*)&g_gen;
    __syncthreads();
    unsigned base = s_base;

    float gi = 0.f, gf = 0.f, gg_ = 0.f, go = 0.f;
    if (tid < 64) {
        const float* Gp = G + (size_t)ub * 2048 + ujg;    // t=0
        gi = Gp[0]; gf = Gp[512]; gg_ = Gp[1024]; go = Gp[1536];
    }

    for (int t = 0; t < 48; ++t) {
        const float* h_in = (t == 0) ? dh : ((t & 1) ? hq : hp);
        float* h_out = (t & 1) ? hp : hq;
        const float4* hin4 = reinterpret_cast<const float4*>(h_in);
#pragma unroll
        for (int i = 0; i < 16; ++i) sm4[tid + i * 128] = hin4[tid + i * 128];
        __syncthreads();

        float acc[64];
#pragma unroll
        for (int i = 0; i < 64; ++i) acc[i] = 0.f;
#pragma unroll
        for (int it = 0; it < 4; ++it) {
            int k4 = it * 32 + kc;
#pragma unroll
            for (int b = 0; b < 16; ++b) {
                float4 hv = sm4[b * 128 + k4];
                acc[0 * 16 + b] += wr[it][0].x * hv.x + wr[it][0].y * hv.y + wr[it][0].z * hv.z + wr[it][0].w * hv.w;
                acc[1 * 16 + b] += wr[it][1].x * hv.x + wr[it][1].y * hv.y + wr[it][1].z * hv.z + wr[it][1].w * hv.w;
                acc[2 * 16 + b] += wr[it][2].x * hv.x + wr[it][2].y * hv.y + wr[it][2].z * hv.z + wr[it][2].w * hv.w;
                acc[3 * 16 + b] += wr[it][3].x * hv.x + wr[it][3].y * hv.y + wr[it][3].z * hv.z + wr[it][3].w * hv.w;
            }
        }
        __syncthreads();
#pragma unroll
        for (int gg = 0; gg < 4; ++gg)
#pragma unroll
            for (int b = 0; b < 16; ++b)
                sm[((ty * 4 + gg) * 16 + b) * 33 + kc] = acc[gg * 16 + b];
        __syncthreads();
#pragma unroll
        for (int rr = 0; rr < 2; ++rr) {
            int o = tid + rr * 128;
            float s = 0.f;
#pragma unroll
            for (int q = 0; q < 32; ++q) s += sm[o * 33 + q];
            redout[o] = s;
        }
        __syncthreads();

        if (tid < 64) {
            float ip = redout[(ujj * 4 + 0) * 16 + ub] + gi;
            float fp = redout[(ujj * 4 + 1) * 16 + ub] + gf;
            float gp = redout[(ujj * 4 + 2) * 16 + ub] + gg_;
            float op = redout[(ujj * 4 + 3) * 16 + ub] + go;
            float c = sigm(fp) * c_sm[tid] + sigm(ip) * tanhf(gp);
            c_sm[tid] = c;
            float h = sigm(op) * tanhf(c);
            h_out[ub * 512 + ujg] = h;
            ds_out[(size_t)(t * 16 + ub) * 512 + ujg] = h;
        }
        if (t < 47) {
            if (tid < 64) {                      // prefetch next step's gates
                const float* Gp = G + (size_t)((t + 1) * 16 + ub) * 2048 + ujg;
                gi = Gp[0]; gf = Gp[512]; gg_ = Gp[1024]; go = Gp[1536];
            }
            grid_bar(base + 1 + t, 128u);
        }
    }
}

// ---------------- launch sequence ----------------
extern "C" void kernel_launch(void* const* d_in, const int* in_sizes, int n_in,
                              void* d_out, int out_size) {
    const int*   x        = (const int*)d_in[0];
    const int*   y        = (const int*)d_in[1];
    const float* enc_emb  = (const float*)d_in[2];
    const float* enc_Wih  = (const float*)d_in[3];
    const float* enc_Whh  = (const float*)d_in[4];
    const float* enc_b    = (const float*)d_in[5];
    const float* dec_emb  = (const float*)d_in[6];
    const float* dec_Wih  = (const float*)d_in[7];
    const float* dec_Whh  = (const float*)d_in[8];
    const float* dec_b    = (const float*)d_in[9];
    const float* lin_W    = (const float*)d_in[10];
    const float* lin_b    = (const float*)d_in[11];
    float* out = (float*)d_out;

    float *act0, *act1, *G, *hp, *hq, *dh, *dc;
    cudaGetSymbolAddress((void**)&act0, g_act0);
    cudaGetSymbolAddress((void**)&act1, g_act1);
    cudaGetSymbolAddress((void**)&G,    g_G);
    cudaGetSymbolAddress((void**)&hp,   g_hping);
    cudaGetSymbolAddress((void**)&hq,   g_hpong);
    cudaGetSymbolAddress((void**)&dh,   g_dech0);
    cudaGetSymbolAddress((void**)&dc,   g_decc0);
    float* bufs[2] = {act0, act1};

    // ---- encoder ----
    embed_k<<<768, 128>>>(enc_emb, x, bufs[0]);
    int p = 0;
    for (int l = 0; l < NL; ++l) {
        gemm_tc<<<dim3(32, 12), 128>>>(bufs[p], enc_Wih + (size_t)l * 1024 * 1024,
                                       enc_b + l * 2048, G,
                                       (size_t)2048, (size_t)32768, (size_t)1);
        enc_layer_k<<<128, 128>>>(enc_Whh + (size_t)l * 2 * 1024 * 256, G,
                                  bufs[1 - p], hp, hq,
                                  dh + l * 8192, dc + l * 8192);
        p ^= 1;
    }

    // ---- decoder ----
    embed_k<<<768, 128>>>(dec_emb, y, bufs[p]);
    for (int l = 0; l < NL; ++l) {
        gemm_tc<<<dim3(32, 12), 128>>>(bufs[p], dec_Wih + (size_t)l * 2048 * 512,
                                       dec_b + l * 2048, G,
                                       (size_t)2048, (size_t)32768, (size_t)1);
        dec_layer_k<<<128, 128>>>(dec_Whh + (size_t)l * 2048 * 512, G,
                                  bufs[1 - p], hp, hq,
                                  dh + l * 8192, dc + l * 8192);
        p ^= 1;
    }

    // ---- final projection: out[b][v][t] ----
    gemm_tc<<<dim3(500, 12), 128>>>(bufs[p], lin_W, lin_b, out,
                                    (size_t)VOUT * 48, (size_t)1, (size_t)48);
}

// round 10
// speedup vs baseline: 1.1592x; 1.0164x over previous
#include <cuda_runtime.h>
#include <math.h>

#define S 48
#define BATCH 16
#define HID 512
#define NL 16
#define M_ROWS 768
#define VOUT 32000

// ---------------- device scratch ----------------
__device__ __align__(128) float g_act0[M_ROWS * HID];
__device__ __align__(128) float g_act1[M_ROWS * HID];
__device__ __align__(128) float g_G[M_ROWS * 2048];
__device__ __align__(128) float g_hping[8192];
__device__ __align__(128) float g_hpong[8192];
__device__ __align__(128) float g_dech0[NL * 8192];
__device__ __align__(128) float g_decc0[NL * 8192];
__device__ __align__(128) float g_dsb[17 * 393216];   // decoder per-layer sequences
// sync: enc dom0 @0, enc dom1 @512, dec @1024 (cnt, gen adjacent like R3; domains on separate lines)
__device__ unsigned g_syn[1536];

// ---------------- R3-protocol barrier, per-domain ----------------
__device__ __forceinline__ void grid_barD(unsigned* cnt, unsigned* gen,
                                          unsigned tgt, unsigned nb) {
    __syncthreads();
    if (threadIdx.x == 0) {
        __threadfence();
        unsigned old = atomicAdd(cnt, 1u);
        if (old == nb - 1u) {
            atomicExch(cnt, 0u);
            __threadfence();
            atomicExch(gen, tgt);
        } else {
            while (*(volatile unsigned*)gen != tgt) { __nanosleep(32); }
        }
        __threadfence();
    }
    __syncthreads();
}

// ---------------- embedding gather ----------------
__global__ void embed_k(const float* __restrict__ emb, const int* __restrict__ ids,
                        float* __restrict__ out) {
    int tb = blockIdx.x;
    int t = tb >> 4, b = tb & 15;
    int id = ids[b * S + t];
    const float4* src = reinterpret_cast<const float4*>(emb) + (size_t)id * (HID / 4);
    float4* dst = reinterpret_cast<float4*>(out) + (size_t)tb * (HID / 4);
    dst[threadIdx.x] = src[threadIdx.x];
}

// -------- fp32 GEMM (R8, measured 56.6us): C[m][n]=A.W^T+b, M=768,K=512 ------
__global__ __launch_bounds__(256) void gemm_k(
    const float* __restrict__ A, const float* __restrict__ W,
    const float* __restrict__ bias, float* __restrict__ C,
    size_t sB, size_t sT, size_t sN) {
    __shared__ float As[2][16 * 68];
    __shared__ float Ws[2][16 * 68];
    int tid = threadIdx.x;
    int tx = tid & 15, ty = tid >> 4;
    int n0 = blockIdx.x * 64, m0 = blockIdx.y * 64;
    int r = tid >> 2, kq = (tid & 3) * 4;

    const float* Arow = A + (size_t)(m0 + r) * 512 + kq;
    const float* Wrow = W + (size_t)(n0 + r) * 512 + kq;

    float4 a = *reinterpret_cast<const float4*>(Arow);
    float4 w = *reinterpret_cast<const float4*>(Wrow);
    As[0][(kq + 0) * 68 + r] = a.x; As[0][(kq + 1) * 68 + r] = a.y;
    As[0][(kq + 2) * 68 + r] = a.z; As[0][(kq + 3) * 68 + r] = a.w;
    Ws[0][(kq + 0) * 68 + r] = w.x; Ws[0][(kq + 1) * 68 + r] = w.y;
    Ws[0][(kq + 2) * 68 + r] = w.z; Ws[0][(kq + 3) * 68 + r] = w.w;
    __syncthreads();

    float acc[16];
#pragma unroll
    for (int i = 0; i < 16; ++i) acc[i] = 0.f;

    for (int k0 = 0; k0 < 512; k0 += 16) {
        int cur = (k0 >> 4) & 1;
        if (k0 + 16 < 512) {
            a = *reinterpret_cast<const float4*>(Arow + k0 + 16);
            w = *reinterpret_cast<const float4*>(Wrow + k0 + 16);
        }
#pragma unroll
        for (int kk = 0; kk < 16; ++kk) {
            float4 av = *reinterpret_cast<const float4*>(&As[cur][kk * 68 + ty * 4]);
            float4 wv = *reinterpret_cast<const float4*>(&Ws[cur][kk * 68 + tx * 4]);
            acc[0]  += av.x * wv.x; acc[1]  += av.x * wv.y; acc[2]  += av.x * wv.z; acc[3]  += av.x * wv.w;
            acc[4]  += av.y * wv.x; acc[5]  += av.y * wv.y; acc[6]  += av.y * wv.z; acc[7]  += av.y * wv.w;
            acc[8]  += av.z * wv.x; acc[9]  += av.z * wv.y; acc[10] += av.z * wv.z; acc[11] += av.z * wv.w;
            acc[12] += av.w * wv.x; acc[13] += av.w * wv.y; acc[14] += av.w * wv.z; acc[15] += av.w * wv.w;
        }
        if (k0 + 16 < 512) {
            int nxt = cur ^ 1;
            As[nxt][(kq + 0) * 68 + r] = a.x; As[nxt][(kq + 1) * 68 + r] = a.y;
            As[nxt][(kq + 2) * 68 + r] = a.z; As[nxt][(kq + 3) * 68 + r] = a.w;
            Ws[nxt][(kq + 0) * 68 + r] = w.x; Ws[nxt][(kq + 1) * 68 + r] = w.y;
            Ws[nxt][(kq + 2) * 68 + r] = w.z; Ws[nxt][(kq + 3) * 68 + r] = w.w;
        }
        __syncthreads();
    }
#pragma unroll
    for (int i = 0; i < 4; ++i) {
        int m = m0 + ty * 4 + i;
        int b = m & 15, t = m >> 4;
#pragma unroll
        for (int jx = 0; jx < 4; ++jx) {
            int n = n0 + tx * 4 + jx;
            C[(size_t)b * sB + (size_t)t * sT + (size_t)n * sN] = acc[i * 4 + jx] + bias[n];
        }
    }
}

__device__ __forceinline__ float sigm(float x) { return 1.f / (1.f + expf(-x)); }

// ======================= persistent encoder layer (R9 body, dual-domain bar) ====
__global__ __launch_bounds__(128, 1) void enc_layer_k(
    const float* __restrict__ Whh,             // (2,1024,256)
    const float* __restrict__ G, float* __restrict__ xs_out,
    float* __restrict__ hp, float* __restrict__ hq,
    float* __restrict__ dh, float* __restrict__ dc) {
    __shared__ float4 sm4[2112];
    __shared__ float redout[256];
    __shared__ float c_sm[64];
    __shared__ unsigned s_base;
    float* sm = (float*)sm4;
    int tid = threadIdx.x;
    int ty = tid >> 5, kc = tid & 31;
    int dir = blockIdx.x >> 6;
    int jb = blockIdx.x & 63;
    int j0 = jb * 4;
    int j = j0 + ty;

    unsigned* cnt = &g_syn[dir * 512];
    unsigned* gen = &g_syn[dir * 512 + 1];

    const float4* w4 = reinterpret_cast<const float4*>(Whh + (size_t)dir * 1024 * 256);
    float4 wr[2][4];
#pragma unroll
    for (int it = 0; it < 2; ++it) {
        int k4 = it * 32 + kc;
        wr[it][0] = w4[(size_t)(0 * 256 + j) * 64 + k4];
        wr[it][1] = w4[(size_t)(1 * 256 + j) * 64 + k4];
        wr[it][2] = w4[(size_t)(2 * 256 + j) * 64 + k4];
        wr[it][3] = w4[(size_t)(3 * 256 + j) * 64 + k4];
    }
    if (tid < 64) c_sm[tid] = 0.f;
    if (tid == 0) s_base = *(volatile unsigned*)gen;
    __syncthreads();
    unsigned base = s_base;

    int ujj = tid >> 4, ub = tid & 15;
    int ujg = j0 + ujj;
    float gi = 0.f, gf = 0.f, gg_ = 0.f, go = 0.f;
    if (tid < 64) {
        int tt0 = dir ? 47 : 0;
        const float* Gp = G + (size_t)(tt0 * 16 + ub) * 2048 + dir * 1024 + ujg;
        gi = Gp[0]; gf = Gp[256]; gg_ = Gp[512]; go = Gp[768];
    }

    for (int t = 0; t < 48; ++t) {
        int tt = dir ? (47 - t) : t;
        float* h_out = (t & 1) ? hp : hq;

        if (t > 0) {
            const float* h_in = (t & 1) ? hq : hp;
            const float4* hin4 = reinterpret_cast<const float4*>(h_in + dir * 4096);
#pragma unroll
            for (int i = 0; i < 8; ++i) sm4[tid + i * 128] = hin4[tid + i * 128];
            __syncthreads();

            float acc[64];
#pragma unroll
            for (int i = 0; i < 64; ++i) acc[i] = 0.f;
#pragma unroll
            for (int it = 0; it < 2; ++it) {
                int k4 = it * 32 + kc;
#pragma unroll
                for (int b = 0; b < 16; ++b) {
                    float4 hv = sm4[b * 64 + k4];
                    acc[0 * 16 + b] += wr[it][0].x * hv.x + wr[it][0].y * hv.y + wr[it][0].z * hv.z + wr[it][0].w * hv.w;
                    acc[1 * 16 + b] += wr[it][1].x * hv.x + wr[it][1].y * hv.y + wr[it][1].z * hv.z + wr[it][1].w * hv.w;
                    acc[2 * 16 + b] += wr[it][2].x * hv.x + wr[it][2].y * hv.y + wr[it][2].z * hv.z + wr[it][2].w * hv.w;
                    acc[3 * 16 + b] += wr[it][3].x * hv.x + wr[it][3].y * hv.y + wr[it][3].z * hv.z + wr[it][3].w * hv.w;
                }
            }
            __syncthreads();
#pragma unroll
            for (int gg = 0; gg < 4; ++gg)
#pragma unroll
                for (int b = 0; b < 16; ++b)
                    sm[((ty * 4 + gg) * 16 + b) * 33 + kc] = acc[gg * 16 + b];
            __syncthreads();
#pragma unroll
            for (int rr = 0; rr < 2; ++rr) {
                int o = tid + rr * 128;
                float s = 0.f;
#pragma unroll
                for (int q = 0; q < 32; ++q) s += sm[o * 33 + q];
                redout[o] = s;
            }
        } else {
#pragma unroll
            for (int rr = 0; rr < 2; ++rr) redout[tid + rr * 128] = 0.f;
        }
        __syncthreads();

        if (tid < 64) {
            float ip = redout[(ujj * 4 + 0) * 16 + ub] + gi;
            float fp = redout[(ujj * 4 + 1) * 16 + ub] + gf;
            float gp = redout[(ujj * 4 + 2) * 16 + ub] + gg_;
            float op = redout[(ujj * 4 + 3) * 16 + ub] + go;
            float c = sigm(fp) * c_sm[tid] + sigm(ip) * tanhf(gp);
            c_sm[tid] = c;
            float h = sigm(op) * tanhf(c);
            h_out[dir * 4096 + ub * 256 + ujg] = h;
            xs_out[(size_t)(tt * 16 + ub) * 512 + dir * 256 + ujg] = h;
            if (t == 47) {
                dh[ub * 512 + dir * 256 + ujg] = h;
                dc[ub * 512 + dir * 256 + ujg] = c;
            }
        }
        if (t < 47) {
            if (tid < 64) {
                int ttn = dir ? (47 - (t + 1)) : (t + 1);
                const float* Gp = G + (size_t)(ttn * 16 + ub) * 2048 + dir * 1024 + ujg;
                gi = Gp[0]; gf = Gp[256]; gg_ = Gp[512]; go = Gp[768];
            }
            grid_barD(cnt, gen, base + 1 + t, 64u);
        }
    }
}

// ======================= decoder wavefront kernel =======================
// 128 CTAs x 256 thr. CTA: layer l = bx>>3, slot s = bx&7 (owns j in [s*64,(s+1)*64)).
// Warp wp: gate g = wp>>1, rows rloc = (wp&1)*32 + lane. Lane owns ONE gate row, all 16 b.
// Cell (l,t): gates = x_t@Wih_l^T + h_{t-1}@Whh_l^T + b; x_t = g_dsb[l][t], h from g_dsb[l+1].
__global__ __launch_bounds__(256, 1) void dec_wave_k(
    const float* __restrict__ Wih, const float* __restrict__ Whh,
    const float* __restrict__ bias,
    const float* __restrict__ dh, const float* __restrict__ dc) {
    __shared__ unsigned long long x2s[128 * 17];   // k-pair chunk [kp][b], padded
    __shared__ float pre[256 * 17];                // gate pre-acts [row][b], padded
    __shared__ float c_sm[1024];
    __shared__ unsigned s_base;

    int tid = threadIdx.x;
    int l = blockIdx.x >> 3, s = blockIdx.x & 7;
    int wp = tid >> 5, lane = tid & 31;
    int g = wp >> 1;
    int rloc = (wp & 1) * 32 + lane;               // 0..63 within j-slice
    int row = g * 512 + s * 64 + rloc;

    const float4* wih4 = reinterpret_cast<const float4*>(Wih + ((size_t)l * 2048 + row) * 512);
    const float4* whh4 = reinterpret_cast<const float4*>(Whh + ((size_t)l * 2048 + row) * 512);
    float bval = bias[l * 2048 + row];

    for (int i = tid; i < 1024; i += 256) {
        int jj = i >> 4, b = i & 15;
        c_sm[i] = dc[(size_t)l * 8192 + b * 512 + s * 64 + jj];
    }
    unsigned* cnt = &g_syn[1024];
    unsigned* gen = &g_syn[1025];
    if (tid == 0) s_base = *(volatile unsigned*)gen;
    __syncthreads();
    unsigned base = s_base;

    float* dsl  = g_dsb + (size_t)l * 393216;
    float* dslo = g_dsb + (size_t)(l + 1) * 393216;
    const float* h0 = dh + (size_t)l * 8192;

    int sb = tid >> 4, si0 = tid & 15;             // staging roles

    for (int w = 0; w < 63; ++w) {
        int t = w - l;
        if (t >= 0 && t < 48) {
            unsigned long long acc[16];
#pragma unroll
            for (int b = 0; b < 16; ++b) acc[b] = 0ull;

#pragma unroll 1
            for (int ch = 0; ch < 4; ++ch) {
                const float* src = (ch < 2)
                    ? (dsl + (size_t)t * 8192 + ch * 256)
                    : ((t == 0) ? (h0 + (ch - 2) * 256)
                                : (dslo + (size_t)(t - 1) * 8192 + (ch - 2) * 256));
                __syncthreads();                   // prior chunk reads done
#pragma unroll
                for (int i = 0; i < 8; ++i) {      // stage 256k x 16b as k-pairs
                    int kp = si0 + i * 16;
                    x2s[kp * 17 + sb] =
                        *reinterpret_cast<const unsigned long long*>(src + sb * 512 + kp * 2);
                }
                __syncthreads();

                const float4* wr4 = (ch < 2) ? (wih4 + ch * 64) : (whh4 + (ch - 2) * 64);
#pragma unroll 4
                for (int kq = 0; kq < 64; ++kq) {
                    float4 w4 = wr4[kq];
                    unsigned long long wa, wb;
                    asm("mov.b64 %0, {%1,%2};" : "=l"(wa) : "f"(w4.x), "f"(w4.y));
                    asm("mov.b64 %0, {%1,%2};" : "=l"(wb) : "f"(w4.z), "f"(w4.w));
                    int p0 = (kq * 2) * 17, p1 = (kq * 2 + 1) * 17;
#pragma unroll
                    for (int b = 0; b < 16; ++b)
                        asm("fma.rn.f32x2 %0, %1, %2, %0;"
                            : "+l"(acc[b]) : "l"(wa), "l"(x2s[p0 + b]));
#pragma unroll
                    for (int b = 0; b < 16; ++b)
                        asm("fma.rn.f32x2 %0, %1, %2, %0;"
                            : "+l"(acc[b]) : "l"(wb), "l"(x2s[p1 + b]));
                }
            }
            // write pre-activations
            int prow = g * 64 + rloc;
#pragma unroll
            for (int b = 0; b < 16; ++b) {
                float lo, hi;
                asm("mov.b64 {%0,%1}, %2;" : "=f"(lo), "=f"(hi) : "l"(acc[b]));
                pre[prow * 17 + b] = lo + hi + bval;
            }
            __syncthreads();
            // LSTM update: 4 (jj,b) pairs per thread
#pragma unroll
            for (int q = 0; q < 4; ++q) {
                int idx = tid + q * 256;           // jj*16+b
                int jj = idx >> 4, b = idx & 15;
                float ip = pre[(jj) * 17 + b];
                float fp = pre[(64 + jj) * 17 + b];
                float gp = pre[(128 + jj) * 17 + b];
                float op = pre[(192 + jj) * 17 + b];
                float c = sigm(fp) * c_sm[idx] + sigm(ip) * tanhf(gp);
                c_sm[idx] = c;
                float h = sigm(op) * tanhf(c);
                dslo[(size_t)t * 8192 + b * 512 + s * 64 + jj] = h;
            }
        }
        if (w < 62) grid_barD(cnt, gen, base + 1 + w, 128u);
    }
}

// ---------------- launch sequence ----------------
extern "C" void kernel_launch(void* const* d_in, const int* in_sizes, int n_in,
                              void* d_out, int out_size) {
    const int*   x        = (const int*)d_in[0];
    const int*   y        = (const int*)d_in[1];
    const float* enc_emb  = (const float*)d_in[2];
    const float* enc_Wih  = (const float*)d_in[3];
    const float* enc_Whh  = (const float*)d_in[4];
    const float* enc_b    = (const float*)d_in[5];
    const float* dec_emb  = (const float*)d_in[6];
    const float* dec_Wih  = (const float*)d_in[7];
    const float* dec_Whh  = (const float*)d_in[8];
    const float* dec_b    = (const float*)d_in[9];
    const float* lin_W    = (const float*)d_in[10];
    const float* lin_b    = (const float*)d_in[11];
    float* out = (float*)d_out;

    float *act0, *act1, *G, *hp, *hq, *dh, *dc, *dsb;
    cudaGetSymbolAddress((void**)&act0, g_act0);
    cudaGetSymbolAddress((void**)&act1, g_act1);
    cudaGetSymbolAddress((void**)&G,    g_G);
    cudaGetSymbolAddress((void**)&hp,   g_hping);
    cudaGetSymbolAddress((void**)&hq,   g_hpong);
    cudaGetSymbolAddress((void**)&dh,   g_dech0);
    cudaGetSymbolAddress((void**)&dc,   g_decc0);
    cudaGetSymbolAddress((void**)&dsb,  g_dsb);
    float* bufs[2] = {act0, act1};

    // ---- encoder ----
    embed_k<<<768, 128>>>(enc_emb, x, bufs[0]);
    int p = 0;
    for (int l = 0; l < NL; ++l) {
        gemm_k<<<dim3(32, 12), 256>>>(bufs[p], enc_Wih + (size_t)l * 1024 * 1024,
                                      enc_b + l * 2048, G,
                                      (size_t)2048, (size_t)32768, (size_t)1);
        enc_layer_k<<<128, 128>>>(enc_Whh + (size_t)l * 2 * 1024 * 256, G,
                                  bufs[1 - p], hp, hq,
                                  dh + l * 8192, dc + l * 8192);
        p ^= 1;
    }

    // ---- decoder: embed + single wavefront kernel ----
    embed_k<<<768, 128>>>(dec_emb, y, dsb);
    dec_wave_k<<<128, 256>>>(dec_Wih, dec_Whh, dec_b, dh, dc);

    // ---- final projection on g_dsb[16]: out[b][v][t] ----
    gemm_k<<<dim3(500, 12), 256>>>(dsb + (size_t)16 * 393216, lin_W, lin_b, out,
                                   (size_t)VOUT * 48, (size_t)1, (size_t)48);
}

// round 11
// speedup vs baseline: 1.3289x; 1.1464x over previous
#include <cuda_runtime.h>
#include <math.h>

#define S 48
#define BATCH 16
#define HID 512
#define NL 16
#define M_ROWS 768
#define VOUT 32000

// ---------------- device scratch ----------------
__device__ __align__(128) float g_act0[M_ROWS * HID];
__device__ __align__(128) float g_act1[M_ROWS * HID];
__device__ __align__(128) float g_G[M_ROWS * 2048];
__device__ __align__(128) float g_hping[8192];
__device__ __align__(128) float g_hpong[8192];
__device__ __align__(128) float g_dech0[NL * 8192];
__device__ __align__(128) float g_decc0[NL * 8192];
__device__ __align__(128) float g_dsb[17 * 393216];   // decoder per-layer sequences
// transposed decoder weights: ULL{W[row][2kp],W[row][2kp+1]} at
// [((l*512 + kp)*8 + s)*256 + row_s], kp<256: ih, kp>=256: hh
__device__ __align__(128) unsigned long long g_WT[16 * 512 * 8 * 256];
// sync: enc dom0 @0, enc dom1 @512, dec @1024
__device__ unsigned g_syn[1536];

// ---------------- R3-protocol barrier, per-domain ----------------
__device__ __forceinline__ void grid_barD(unsigned* cnt, unsigned* gen,
                                          unsigned tgt, unsigned nb) {
    __syncthreads();
    if (threadIdx.x == 0) {
        __threadfence();
        unsigned old = atomicAdd(cnt, 1u);
        if (old == nb - 1u) {
            atomicExch(cnt, 0u);
            __threadfence();
            atomicExch(gen, tgt);
        } else {
            while (*(volatile unsigned*)gen != tgt) { __nanosleep(32); }
        }
        __threadfence();
    }
    __syncthreads();
}

// ---------------- embedding gather ----------------
__global__ void embed_k(const float* __restrict__ emb, const int* __restrict__ ids,
                        float* __restrict__ out) {
    int tb = blockIdx.x;
    int t = tb >> 4, b = tb & 15;
    int id = ids[b * S + t];
    const float4* src = reinterpret_cast<const float4*>(emb) + (size_t)id * (HID / 4);
    float4* dst = reinterpret_cast<float4*>(out) + (size_t)tb * (HID / 4);
    dst[threadIdx.x] = src[threadIdx.x];
}

// ---------------- one-time decoder weight transpose (coalesced, tiled) ----------
__global__ __launch_bounds__(256) void transpose_w_k(
    const float* __restrict__ Wih, const float* __restrict__ Whh,
    unsigned long long* __restrict__ WT) {
    __shared__ float sm[64 * 132];
    int bx = blockIdx.x;
    int kb = bx & 3, g = (bx >> 2) & 3, s = (bx >> 4) & 7, mat = (bx >> 7) & 1, l = bx >> 8;
    const float* src = (mat ? Whh : Wih) + (size_t)l * 2048 * 512;
    int tid = threadIdx.x;
    int k4 = tid & 31, r0 = tid >> 5;
#pragma unroll
    for (int it = 0; it < 8; ++it) {
        int rloc = r0 + it * 8;
        int rowg = g * 512 + s * 64 + rloc;
        float4 v = *reinterpret_cast<const float4*>(src + (size_t)rowg * 512 + kb * 128 + k4 * 4);
        *reinterpret_cast<float4*>(&sm[rloc * 132 + k4 * 4]) = v;
    }
    __syncthreads();
    int rl = tid & 63, kp0 = tid >> 6;
#pragma unroll
    for (int it = 0; it < 16; ++it) {
        int kpl = kp0 + it * 4;
        float lo = sm[rl * 132 + kpl * 2], hi = sm[rl * 132 + kpl * 2 + 1];
        unsigned long long v;
        asm("mov.b64 %0, {%1,%2};" : "=l"(v) : "f"(lo), "f"(hi));
        int kp = mat * 256 + kb * 64 + kpl;
        WT[(((size_t)l * 512 + kp) * 8 + s) * 256 + g * 64 + rl] = v;
    }
}

// -------- fp32 GEMM (measured 56us): C[m][n]=A.W^T+b, M=768,K=512 ------
__global__ __launch_bounds__(256) void gemm_k(
    const float* __restrict__ A, const float* __restrict__ W,
    const float* __restrict__ bias, float* __restrict__ C,
    size_t sB, size_t sT, size_t sN) {
    __shared__ float As[2][16 * 68];
    __shared__ float Ws[2][16 * 68];
    int tid = threadIdx.x;
    int tx = tid & 15, ty = tid >> 4;
    int n0 = blockIdx.x * 64, m0 = blockIdx.y * 64;
    int r = tid >> 2, kq = (tid & 3) * 4;

    const float* Arow = A + (size_t)(m0 + r) * 512 + kq;
    const float* Wrow = W + (size_t)(n0 + r) * 512 + kq;

    float4 a = *reinterpret_cast<const float4*>(Arow);
    float4 w = *reinterpret_cast<const float4*>(Wrow);
    As[0][(kq + 0) * 68 + r] = a.x; As[0][(kq + 1) * 68 + r] = a.y;
    As[0][(kq + 2) * 68 + r] = a.z; As[0][(kq + 3) * 68 + r] = a.w;
    Ws[0][(kq + 0) * 68 + r] = w.x; Ws[0][(kq + 1) * 68 + r] = w.y;
    Ws[0][(kq + 2) * 68 + r] = w.z; Ws[0][(kq + 3) * 68 + r] = w.w;
    __syncthreads();

    float acc[16];
#pragma unroll
    for (int i = 0; i < 16; ++i) acc[i] = 0.f;

    for (int k0 = 0; k0 < 512; k0 += 16) {
        int cur = (k0 >> 4) & 1;
        if (k0 + 16 < 512) {
            a = *reinterpret_cast<const float4*>(Arow + k0 + 16);
            w = *reinterpret_cast<const float4*>(Wrow + k0 + 16);
        }
#pragma unroll
        for (int kk = 0; kk < 16; ++kk) {
            float4 av = *reinterpret_cast<const float4*>(&As[cur][kk * 68 + ty * 4]);
            float4 wv = *reinterpret_cast<const float4*>(&Ws[cur][kk * 68 + tx * 4]);
            acc[0]  += av.x * wv.x; acc[1]  += av.x * wv.y; acc[2]  += av.x * wv.z; acc[3]  += av.x * wv.w;
            acc[4]  += av.y * wv.x; acc[5]  += av.y * wv.y; acc[6]  += av.y * wv.z; acc[7]  += av.y * wv.w;
            acc[8]  += av.z * wv.x; acc[9]  += av.z * wv.y; acc[10] += av.z * wv.z; acc[11] += av.z * wv.w;
            acc[12] += av.w * wv.x; acc[13] += av.w * wv.y; acc[14] += av.w * wv.z; acc[15] += av.w * wv.w;
        }
        if (k0 + 16 < 512) {
            int nxt = cur ^ 1;
            As[nxt][(kq + 0) * 68 + r] = a.x; As[nxt][(kq + 1) * 68 + r] = a.y;
            As[nxt][(kq + 2) * 68 + r] = a.z; As[nxt][(kq + 3) * 68 + r] = a.w;
            Ws[nxt][(kq + 0) * 68 + r] = w.x; Ws[nxt][(kq + 1) * 68 + r] = w.y;
            Ws[nxt][(kq + 2) * 68 + r] = w.z; Ws[nxt][(kq + 3) * 68 + r] = w.w;
        }
        __syncthreads();
    }
#pragma unroll
    for (int i = 0; i < 4; ++i) {
        int m = m0 + ty * 4 + i;
        int b = m & 15, t = m >> 4;
#pragma unroll
        for (int jx = 0; jx < 4; ++jx) {
            int n = n0 + tx * 4 + jx;
            C[(size_t)b * sB + (size_t)t * sT + (size_t)n * sN] = acc[i * 4 + jx] + bias[n];
        }
    }
}

__device__ __forceinline__ float sigm(float x) { return 1.f / (1.f + expf(-x)); }

// ======================= persistent encoder layer (unchanged from R10) ====
__global__ __launch_bounds__(128, 1) void enc_layer_k(
    const float* __restrict__ Whh,             // (2,1024,256)
    const float* __restrict__ G, float* __restrict__ xs_out,
    float* __restrict__ hp, float* __restrict__ hq,
    float* __restrict__ dh, float* __restrict__ dc) {
    __shared__ float4 sm4[2112];
    __shared__ float redout[256];
    __shared__ float c_sm[64];
    __shared__ unsigned s_base;
    float* sm = (float*)sm4;
    int tid = threadIdx.x;
    int ty = tid >> 5, kc = tid & 31;
    int dir = blockIdx.x >> 6;
    int jb = blockIdx.x & 63;
    int j0 = jb * 4;
    int j = j0 + ty;

    unsigned* cnt = &g_syn[dir * 512];
    unsigned* gen = &g_syn[dir * 512 + 1];

    const float4* w4 = reinterpret_cast<const float4*>(Whh + (size_t)dir * 1024 * 256);
    float4 wr[2][4];
#pragma unroll
    for (int it = 0; it < 2; ++it) {
        int k4 = it * 32 + kc;
        wr[it][0] = w4[(size_t)(0 * 256 + j) * 64 + k4];
        wr[it][1] = w4[(size_t)(1 * 256 + j) * 64 + k4];
        wr[it][2] = w4[(size_t)(2 * 256 + j) * 64 + k4];
        wr[it][3] = w4[(size_t)(3 * 256 + j) * 64 + k4];
    }
    if (tid < 64) c_sm[tid] = 0.f;
    if (tid == 0) s_base = *(volatile unsigned*)gen;
    __syncthreads();
    unsigned base = s_base;

    int ujj = tid >> 4, ub = tid & 15;
    int ujg = j0 + ujj;
    float gi = 0.f, gf = 0.f, gg_ = 0.f, go = 0.f;
    if (tid < 64) {
        int tt0 = dir ? 47 : 0;
        const float* Gp = G + (size_t)(tt0 * 16 + ub) * 2048 + dir * 1024 + ujg;
        gi = Gp[0]; gf = Gp[256]; gg_ = Gp[512]; go = Gp[768];
    }

    for (int t = 0; t < 48; ++t) {
        int tt = dir ? (47 - t) : t;
        float* h_out = (t & 1) ? hp : hq;

        if (t > 0) {
            const float* h_in = (t & 1) ? hq : hp;
            const float4* hin4 = reinterpret_cast<const float4*>(h_in + dir * 4096);
#pragma unroll
            for (int i = 0; i < 8; ++i) sm4[tid + i * 128] = hin4[tid + i * 128];
            __syncthreads();

            float acc[64];
#pragma unroll
            for (int i = 0; i < 64; ++i) acc[i] = 0.f;
#pragma unroll
            for (int it = 0; it < 2; ++it) {
                int k4 = it * 32 + kc;
#pragma unroll
                for (int b = 0; b < 16; ++b) {
                    float4 hv = sm4[b * 64 + k4];
                    acc[0 * 16 + b] += wr[it][0].x * hv.x + wr[it][0].y * hv.y + wr[it][0].z * hv.z + wr[it][0].w * hv.w;
                    acc[1 * 16 + b] += wr[it][1].x * hv.x + wr[it][1].y * hv.y + wr[it][1].z * hv.z + wr[it][1].w * hv.w;
                    acc[2 * 16 + b] += wr[it][2].x * hv.x + wr[it][2].y * hv.y + wr[it][2].z * hv.z + wr[it][2].w * hv.w;
                    acc[3 * 16 + b] += wr[it][3].x * hv.x + wr[it][3].y * hv.y + wr[it][3].z * hv.z + wr[it][3].w * hv.w;
                }
            }
            __syncthreads();
#pragma unroll
            for (int gg = 0; gg < 4; ++gg)
#pragma unroll
                for (int b = 0; b < 16; ++b)
                    sm[((ty * 4 + gg) * 16 + b) * 33 + kc] = acc[gg * 16 + b];
            __syncthreads();
#pragma unroll
            for (int rr = 0; rr < 2; ++rr) {
                int o = tid + rr * 128;
                float ss = 0.f;
#pragma unroll
                for (int q = 0; q < 32; ++q) ss += sm[o * 33 + q];
                redout[o] = ss;
            }
        } else {
#pragma unroll
            for (int rr = 0; rr < 2; ++rr) redout[tid + rr * 128] = 0.f;
        }
        __syncthreads();

        if (tid < 64) {
            float ip = redout[(ujj * 4 + 0) * 16 + ub] + gi;
            float fp = redout[(ujj * 4 + 1) * 16 + ub] + gf;
            float gp = redout[(ujj * 4 + 2) * 16 + ub] + gg_;
            float op = redout[(ujj * 4 + 3) * 16 + ub] + go;
            float c = sigm(fp) * c_sm[tid] + sigm(ip) * tanhf(gp);
            c_sm[tid] = c;
            float h = sigm(op) * tanhf(c);
            h_out[dir * 4096 + ub * 256 + ujg] = h;
            xs_out[(size_t)(tt * 16 + ub) * 512 + dir * 256 + ujg] = h;
            if (t == 47) {
                dh[ub * 512 + dir * 256 + ujg] = h;
                dc[ub * 512 + dir * 256 + ujg] = c;
            }
        }
        if (t < 47) {
            if (tid < 64) {
                int ttn = dir ? (47 - (t + 1)) : (t + 1);
                const float* Gp = G + (size_t)(ttn * 16 + ub) * 2048 + dir * 1024 + ujg;
                gi = Gp[0]; gf = Gp[256]; gg_ = Gp[512]; go = Gp[768];
            }
            grid_barD(cnt, gen, base + 1 + t, 64u);
        }
    }
}

// ======================= decoder wavefront v2 (coalesced WT, 2 rows/thread) ====
// 128 CTAs x 256 thr. CTA: layer l = bx>>3, slot s = bx&7 (rows = 4 gates x 64 j).
// Thread: rp = tid&127 -> slice rows 2rp,2rp+1; kh = tid>>7 -> 0:ih(x) 1:hh(h).
#define FMA2(acc, wv, xv) asm("fma.rn.f32x2 %0, %1, %2, %0;" : "+l"(acc) : "l"(wv), "l"(xv))
__global__ __launch_bounds__(256, 1) void dec_wave_k(
    const unsigned long long* __restrict__ WT,
    const float* __restrict__ bias,
    const float* __restrict__ dh, const float* __restrict__ dc) {
    __shared__ unsigned long long xh[2176 * 2];    // xbuf[128][17], hbuf[128][17]
    __shared__ float c_sm[1024];
    __shared__ unsigned s_base;
    float* pre = reinterpret_cast<float*>(xh);     // overlay on xbuf: [256 rows][17]

    int tid = threadIdx.x;
    int l = blockIdx.x >> 3, s = blockIdx.x & 7;
    int rp = tid & 127;
    int kh = tid >> 7;

    int g0 = (2 * rp) >> 6;                        // rows 2rp,2rp+1 share a gate
    int rl0 = (2 * rp) & 63;
    int rowg = g0 * 512 + s * 64 + rl0;
    float bv0 = bias[l * 2048 + rowg];
    float bv1 = bias[l * 2048 + rowg + 1];

    for (int i = tid; i < 1024; i += 256) {
        int jj = i >> 4, b = i & 15;
        c_sm[i] = dc[(size_t)l * 8192 + b * 512 + s * 64 + jj];
    }
    unsigned* cnt = &g_syn[1024];
    unsigned* gen = &g_syn[1025];
    if (tid == 0) s_base = *(volatile unsigned*)gen;
    __syncthreads();
    unsigned base = s_base;

    const float* dsl = g_dsb + (size_t)l * 393216;
    float* dslo = g_dsb + (size_t)(l + 1) * 393216;
    const float* h0 = dh + (size_t)l * 8192;

    int sb = tid >> 4, si = tid & 15;
    unsigned long long* xbuf = xh;
    unsigned long long* hbuf = xh + 2176;
    unsigned long long* mybuf = kh ? hbuf : xbuf;

    // WT as ulonglong2: idx2(kp) = l*524288 + s*128 + kp*1024 + rp
    const ulonglong2* WT2 = reinterpret_cast<const ulonglong2*>(WT);
    size_t w2base = (size_t)l * 524288 + (size_t)s * 128 + (size_t)rp;

    for (int w = 0; w < 63; ++w) {
        int t = w - l;
        if (t >= 0 && t < 48) {
            unsigned long long acc0[16], acc1[16];
#pragma unroll
            for (int b = 0; b < 16; ++b) { acc0[b] = 0ull; acc1[b] = 0ull; }

            const float* xsrc = dsl + (size_t)t * 8192;
            const float* hsrc = (t == 0) ? h0 : (dslo + (size_t)(t - 1) * 8192);

#pragma unroll 1
            for (int half = 0; half < 2; ++half) {
                __syncthreads();                   // prior readers of buffers done
#pragma unroll
                for (int i = 0; i < 8; ++i) {      // stage 256-k chunks of x and h
                    int kp = si + i * 16;
                    xbuf[kp * 17 + sb] = *reinterpret_cast<const unsigned long long*>(
                        xsrc + sb * 512 + half * 256 + kp * 2);
                    hbuf[kp * 17 + sb] = *reinterpret_cast<const unsigned long long*>(
                        hsrc + sb * 512 + half * 256 + kp * 2);
                }
                __syncthreads();

                size_t wb = w2base + (size_t)(kh * 256 + half * 128) * 1024;
#pragma unroll 4
                for (int kq = 0; kq < 128; ++kq) {
                    ulonglong2 wv = WT2[wb + (size_t)kq * 1024];
                    int p = kq * 17;
#pragma unroll
                    for (int b = 0; b < 16; ++b) {
                        unsigned long long xv = mybuf[p + b];
                        FMA2(acc0[b], wv.x, xv);
                        FMA2(acc1[b], wv.y, xv);
                    }
                }
            }
            __syncthreads();                       // all buffer reads done; overlay pre

            int pr0 = (2 * rp) * 17, pr1 = (2 * rp + 1) * 17;
            if (kh == 0) {
#pragma unroll
                for (int b = 0; b < 16; ++b) {
                    float lo, hi;
                    asm("mov.b64 {%0,%1}, %2;" : "=f"(lo), "=f"(hi) : "l"(acc0[b]));
                    pre[pr0 + b] = lo + hi;
                    asm("mov.b64 {%0,%1}, %2;" : "=f"(lo), "=f"(hi) : "l"(acc1[b]));
                    pre[pr1 + b] = lo + hi;
                }
            }
            __syncthreads();
            if (kh == 1) {
#pragma unroll
                for (int b = 0; b < 16; ++b) {
                    float lo, hi;
                    asm("mov.b64 {%0,%1}, %2;" : "=f"(lo), "=f"(hi) : "l"(acc0[b]));
                    pre[pr0 + b] += lo + hi + bv0;
                    asm("mov.b64 {%0,%1}, %2;" : "=f"(lo), "=f"(hi) : "l"(acc1[b]));
                    pre[pr1 + b] += lo + hi + bv1;
                }
            }
            __syncthreads();
#pragma unroll
            for (int q = 0; q < 4; ++q) {
                int idx = tid + q * 256;           // jj*16+b
                int jj = idx >> 4, b = idx & 15;
                float ip = pre[(jj) * 17 + b];
                float fp = pre[(64 + jj) * 17 + b];
                float gp = pre[(128 + jj) * 17 + b];
                float op = pre[(192 + jj) * 17 + b];
                float c = sigm(fp) * c_sm[idx] + sigm(ip) * tanhf(gp);
                c_sm[idx] = c;
                float h = sigm(op) * tanhf(c);
                dslo[(size_t)t * 8192 + b * 512 + s * 64 + jj] = h;
            }
        }
        if (w < 62) grid_barD(cnt, gen, base + 1 + w, 128u);
    }
}

// ---------------- launch sequence ----------------
extern "C" void kernel_launch(void* const* d_in, const int* in_sizes, int n_in,
                              void* d_out, int out_size) {
    const int*   x        = (const int*)d_in[0];
    const int*   y        = (const int*)d_in[1];
    const float* enc_emb  = (const float*)d_in[2];
    const float* enc_Wih  = (const float*)d_in[3];
    const float* enc_Whh  = (const float*)d_in[4];
    const float* enc_b    = (const float*)d_in[5];
    const float* dec_emb  = (const float*)d_in[6];
    const float* dec_Wih  = (const float*)d_in[7];
    const float* dec_Whh  = (const float*)d_in[8];
    const float* dec_b    = (const float*)d_in[9];
    const float* lin_W    = (const float*)d_in[10];
    const float* lin_b    = (const float*)d_in[11];
    float* out = (float*)d_out;

    float *act0, *act1, *G, *hp, *hq, *dh, *dc, *dsb;
    unsigned long long* WT;
    cudaGetSymbolAddress((void**)&act0, g_act0);
    cudaGetSymbolAddress((void**)&act1, g_act1);
    cudaGetSymbolAddress((void**)&G,    g_G);
    cudaGetSymbolAddress((void**)&hp,   g_hping);
    cudaGetSymbolAddress((void**)&hq,   g_hpong);
    cudaGetSymbolAddress((void**)&dh,   g_dech0);
    cudaGetSymbolAddress((void**)&dc,   g_decc0);
    cudaGetSymbolAddress((void**)&dsb,  g_dsb);
    cudaGetSymbolAddress((void**)&WT,   g_WT);
    float* bufs[2] = {act0, act1};

    // ---- one-time decoder weight transpose (independent of everything) ----
    transpose_w_k<<<4096, 256>>>(dec_Wih, dec_Whh, WT);

    // ---- encoder ----
    embed_k<<<768, 128>>>(enc_emb, x, bufs[0]);
    int p = 0;
    for (int l = 0; l < NL; ++l) {
        gemm_k<<<dim3(32, 12), 256>>>(bufs[p], enc_Wih + (size_t)l * 1024 * 1024,
                                      enc_b + l * 2048, G,
                                      (size_t)2048, (size_t)32768, (size_t)1);
        enc_layer_k<<<128, 128>>>(enc_Whh + (size_t)l * 2 * 1024 * 256, G,
                                  bufs[1 - p], hp, hq,
                                  dh + l * 8192, dc + l * 8192);
        p ^= 1;
    }

    // ---- decoder: embed + single wavefront kernel ----
    embed_k<<<768, 128>>>(dec_emb, y, dsb);
    dec_wave_k<<<128, 256>>>(WT, dec_b, dh, dc);

    // ---- final projection on g_dsb[16]: out[b][v][t] ----
    gemm_k<<<dim3(500, 12), 256>>>(dsb + (size_t)16 * 393216, lin_W, lin_b, out,
                                   (size_t)VOUT * 48, (size_t)1, (size_t)48);
}

// round 13
// speedup vs baseline: 1.5306x; 1.1517x over previous
#include <cuda_runtime.h>
#include <math.h>

#define S 48
#define BATCH 16
#define HID 512
#define NL 16
#define M_ROWS 768
#define VOUT 32000

// ---------------- device scratch ----------------
__device__ __align__(128) float g_act0[M_ROWS * HID];
__device__ __align__(128) float g_act1[M_ROWS * HID];
__device__ __align__(128) float g_G[M_ROWS * 2048];
__device__ __align__(128) float g_hping[8192];
__device__ __align__(128) float g_hpong[8192];
__device__ __align__(128) float g_dech0[NL * 8192];
__device__ __align__(128) float g_decc0[NL * 8192];
__device__ __align__(128) float g_dsb[17 * 393216];   // decoder per-layer sequences
// transposed decoder weights (k-pair ULLs)
__device__ __align__(128) unsigned long long g_WT[16 * 512 * 8 * 256];
// sync: enc dom0 @0, enc dom1 @512, dec @1024
__device__ unsigned g_syn[1536];

// ---------------- R3-protocol barrier, per-domain ----------------
__device__ __forceinline__ void grid_barD(unsigned* cnt, unsigned* gen,
                                          unsigned tgt, unsigned nb) {
    __syncthreads();
    if (threadIdx.x == 0) {
        __threadfence();
        unsigned old = atomicAdd(cnt, 1u);
        if (old == nb - 1u) {
            atomicExch(cnt, 0u);
            __threadfence();
            atomicExch(gen, tgt);
        } else {
            while (*(volatile unsigned*)gen != tgt) { __nanosleep(32); }
        }
        __threadfence();
    }
    __syncthreads();
}

// ---------------- embedding gather ----------------
__global__ void embed_k(const float* __restrict__ emb, const int* __restrict__ ids,
                        float* __restrict__ out) {
    int tb = blockIdx.x;
    int t = tb >> 4, b = tb & 15;
    int id = ids[b * S + t];
    const float4* src = reinterpret_cast<const float4*>(emb) + (size_t)id * (HID / 4);
    float4* dst = reinterpret_cast<float4*>(out) + (size_t)tb * (HID / 4);
    dst[threadIdx.x] = src[threadIdx.x];
}

// ---------------- one-time decoder weight transpose ----------
__global__ __launch_bounds__(256) void transpose_w_k(
    const float* __restrict__ Wih, const float* __restrict__ Whh,
    unsigned long long* __restrict__ WT) {
    __shared__ float sm[64 * 132];
    int bx = blockIdx.x;
    int kb = bx & 3, g = (bx >> 2) & 3, s = (bx >> 4) & 7, mat = (bx >> 7) & 1, l = bx >> 8;
    const float* src = (mat ? Whh : Wih) + (size_t)l * 2048 * 512;
    int tid = threadIdx.x;
    int k4 = tid & 31, r0 = tid >> 5;
#pragma unroll
    for (int it = 0; it < 8; ++it) {
        int rloc = r0 + it * 8;
        int rowg = g * 512 + s * 64 + rloc;
        float4 v = *reinterpret_cast<const float4*>(src + (size_t)rowg * 512 + kb * 128 + k4 * 4);
        *reinterpret_cast<float4*>(&sm[rloc * 132 + k4 * 4]) = v;
    }
    __syncthreads();
    int rl = tid & 63, kp0 = tid >> 6;
#pragma unroll
    for (int it = 0; it < 16; ++it) {
        int kpl = kp0 + it * 4;
        float lo = sm[rl * 132 + kpl * 2], hi = sm[rl * 132 + kpl * 2 + 1];
        unsigned long long v;
        asm("mov.b64 %0, {%1,%2};" : "=l"(v) : "f"(lo), "f"(hi));
        int kp = mat * 256 + kb * 64 + kpl;
        WT[(((size_t)l * 512 + kp) * 8 + s) * 256 + g * 64 + rl] = v;
    }
}

// -------- fp32 GEMM (measured 56us): C[m][n]=A.W^T+b, M=768,K=512 ------
__global__ __launch_bounds__(256) void gemm_k(
    const float* __restrict__ A, const float* __restrict__ W,
    const float* __restrict__ bias, float* __restrict__ C,
    size_t sB, size_t sT, size_t sN) {
    __shared__ float As[2][16 * 68];
    __shared__ float Ws[2][16 * 68];
    int tid = threadIdx.x;
    int tx = tid & 15, ty = tid >> 4;
    int n0 = blockIdx.x * 64, m0 = blockIdx.y * 64;
    int r = tid >> 2, kq = (tid & 3) * 4;

    const float* Arow = A + (size_t)(m0 + r) * 512 + kq;
    const float* Wrow = W + (size_t)(n0 + r) * 512 + kq;

    float4 a = *reinterpret_cast<const float4*>(Arow);
    float4 w = *reinterpret_cast<const float4*>(Wrow);
    As[0][(kq + 0) * 68 + r] = a.x; As[0][(kq + 1) * 68 + r] = a.y;
    As[0][(kq + 2) * 68 + r] = a.z; As[0][(kq + 3) * 68 + r] = a.w;
    Ws[0][(kq + 0) * 68 + r] = w.x; Ws[0][(kq + 1) * 68 + r] = w.y;
    Ws[0][(kq + 2) * 68 + r] = w.z; Ws[0][(kq + 3) * 68 + r] = w.w;
    __syncthreads();

    float acc[16];
#pragma unroll
    for (int i = 0; i < 16; ++i) acc[i] = 0.f;

    for (int k0 = 0; k0 < 512; k0 += 16) {
        int cur = (k0 >> 4) & 1;
        if (k0 + 16 < 512) {
            a = *reinterpret_cast<const float4*>(Arow + k0 + 16);
            w = *reinterpret_cast<const float4*>(Wrow + k0 + 16);
        }
#pragma unroll
        for (int kk = 0; kk < 16; ++kk) {
            float4 av = *reinterpret_cast<const float4*>(&As[cur][kk * 68 + ty * 4]);
            float4 wv = *reinterpret_cast<const float4*>(&Ws[cur][kk * 68 + tx * 4]);
            acc[0]  += av.x * wv.x; acc[1]  += av.x * wv.y; acc[2]  += av.x * wv.z; acc[3]  += av.x * wv.w;
            acc[4]  += av.y * wv.x; acc[5]  += av.y * wv.y; acc[6]  += av.y * wv.z; acc[7]  += av.y * wv.w;
            acc[8]  += av.z * wv.x; acc[9]  += av.z * wv.y; acc[10] += av.z * wv.z; acc[11] += av.z * wv.w;
            acc[12] += av.w * wv.x; acc[13] += av.w * wv.y; acc[14] += av.w * wv.z; acc[15] += av.w * wv.w;
        }
        if (k0 + 16 < 512) {
            int nxt = cur ^ 1;
            As[nxt][(kq + 0) * 68 + r] = a.x; As[nxt][(kq + 1) * 68 + r] = a.y;
            As[nxt][(kq + 2) * 68 + r] = a.z; As[nxt][(kq + 3) * 68 + r] = a.w;
            Ws[nxt][(kq + 0) * 68 + r] = w.x; Ws[nxt][(kq + 1) * 68 + r] = w.y;
            Ws[nxt][(kq + 2) * 68 + r] = w.z; Ws[nxt][(kq + 3) * 68 + r] = w.w;
        }
        __syncthreads();
    }
#pragma unroll
    for (int i = 0; i < 4; ++i) {
        int m = m0 + ty * 4 + i;
        int b = m & 15, t = m >> 4;
#pragma unroll
        for (int jx = 0; jx < 4; ++jx) {
            int n = n0 + tx * 4 + jx;
            C[(size_t)b * sB + (size_t)t * sT + (size_t)n * sN] = acc[i * 4 + jx] + bias[n];
        }
    }
}

// -------- projection GEMM: A rows are (b*48+t), coalesced out[b][v][t] stores ------
__global__ __launch_bounds__(256) void proj_k(
    const float* __restrict__ A, const float* __restrict__ W,
    const float* __restrict__ bias, float* __restrict__ C) {
    __shared__ float As[2][16 * 68];
    __shared__ float Ws[2][16 * 68];
    int tid = threadIdx.x;
    int tx = tid & 15, ty = tid >> 4;
    int n0 = blockIdx.x * 64, m0 = blockIdx.y * 64;
    int r = tid >> 2, kq = (tid & 3) * 4;

    const float* Arow = A + (size_t)(m0 + r) * 512 + kq;
    const float* Wrow = W + (size_t)(n0 + r) * 512 + kq;

    float4 a = *reinterpret_cast<const float4*>(Arow);
    float4 w = *reinterpret_cast<const float4*>(Wrow);
    As[0][(kq + 0) * 68 + r] = a.x; As[0][(kq + 1) * 68 + r] = a.y;
    As[0][(kq + 2) * 68 + r] = a.z; As[0][(kq + 3) * 68 + r] = a.w;
    Ws[0][(kq + 0) * 68 + r] = w.x; Ws[0][(kq + 1) * 68 + r] = w.y;
    Ws[0][(kq + 2) * 68 + r] = w.z; Ws[0][(kq + 3) * 68 + r] = w.w;
    __syncthreads();

    float acc[16];
#pragma unroll
    for (int i = 0; i < 16; ++i) acc[i] = 0.f;

    for (int k0 = 0; k0 < 512; k0 += 16) {
        int cur = (k0 >> 4) & 1;
        if (k0 + 16 < 512) {
            a = *reinterpret_cast<const float4*>(Arow + k0 + 16);
            w = *reinterpret_cast<const float4*>(Wrow + k0 + 16);
        }
#pragma unroll
        for (int kk = 0; kk < 16; ++kk) {
            float4 av = *reinterpret_cast<const float4*>(&As[cur][kk * 68 + ty * 4]);
            float4 wv = *reinterpret_cast<const float4*>(&Ws[cur][kk * 68 + tx * 4]);
            acc[0]  += av.x * wv.x; acc[1]  += av.x * wv.y; acc[2]  += av.x * wv.z; acc[3]  += av.x * wv.w;
            acc[4]  += av.y * wv.x; acc[5]  += av.y * wv.y; acc[6]  += av.y * wv.z; acc[7]  += av.y * wv.w;
            acc[8]  += av.z * wv.x; acc[9]  += av.z * wv.y; acc[10] += av.z * wv.z; acc[11] += av.z * wv.w;
            acc[12] += av.w * wv.x; acc[13] += av.w * wv.y; acc[14] += av.w * wv.z; acc[15] += av.w * wv.w;
        }
        if (k0 + 16 < 512) {
            int nxt = cur ^ 1;
            As[nxt][(kq + 0) * 68 + r] = a.x; As[nxt][(kq + 1) * 68 + r] = a.y;
            As[nxt][(kq + 2) * 68 + r] = a.z; As[nxt][(kq + 3) * 68 + r] = a.w;
            Ws[nxt][(kq + 0) * 68 + r] = w.x; Ws[nxt][(kq + 1) * 68 + r] = w.y;
            Ws[nxt][(kq + 2) * 68 + r] = w.z; Ws[nxt][(kq + 3) * 68 + r] = w.w;
        }
        __syncthreads();
    }
    // stage tile to smem (overlay As/Ws: 64*68 floats), then coalesced store
    float* smo = &As[0][0];
#pragma unroll
    for (int i = 0; i < 4; ++i)
#pragma unroll
        for (int jx = 0; jx < 4; ++jx)
            smo[(ty * 4 + i) * 68 + tx * 4 + jx] = acc[i * 4 + jx] + bias[n0 + tx * 4 + jx];
    __syncthreads();
#pragma unroll
    for (int it = 0; it < 16; ++it) {
        int idx = tid + it * 256;
        int m = idx & 63, n = idx >> 6;
        int mg = m0 + m;
        int b = mg / 48, t = mg - b * 48;
        C[(size_t)b * ((size_t)VOUT * 48) + (size_t)(n0 + n) * 48 + t] = smo[m * 68 + n];
    }
}

__device__ __forceinline__ float sigm(float x) { return 1.f / (1.f + expf(-x)); }

// ======================= persistent encoder layer (unchanged) ====
__global__ __launch_bounds__(128, 1) void enc_layer_k(
    const float* __restrict__ Whh,             // (2,1024,256)
    const float* __restrict__ G, float* __restrict__ xs_out,
    float* __restrict__ hp, float* __restrict__ hq,
    float* __restrict__ dh, float* __restrict__ dc) {
    __shared__ float4 sm4[2112];
    __shared__ float redout[256];
    __shared__ float c_sm[64];
    __shared__ unsigned s_base;
    float* sm = (float*)sm4;
    int tid = threadIdx.x;
    int ty = tid >> 5, kc = tid & 31;
    int dir = blockIdx.x >> 6;
    int jb = blockIdx.x & 63;
    int j0 = jb * 4;
    int j = j0 + ty;

    unsigned* cnt = &g_syn[dir * 512];
    unsigned* gen = &g_syn[dir * 512 + 1];

    const float4* w4 = reinterpret_cast<const float4*>(Whh + (size_t)dir * 1024 * 256);
    float4 wr[2][4];
#pragma unroll
    for (int it = 0; it < 2; ++it) {
        int k4 = it * 32 + kc;
        wr[it][0] = w4[(size_t)(0 * 256 + j) * 64 + k4];
        wr[it][1] = w4[(size_t)(1 * 256 + j) * 64 + k4];
        wr[it][2] = w4[(size_t)(2 * 256 + j) * 64 + k4];
        wr[it][3] = w4[(size_t)(3 * 256 + j) * 64 + k4];
    }
    if (tid < 64) c_sm[tid] = 0.f;
    if (tid == 0) s_base = *(volatile unsigned*)gen;
    __syncthreads();
    unsigned base = s_base;

    int ujj = tid >> 4, ub = tid & 15;
    int ujg = j0 + ujj;
    float gi = 0.f, gf = 0.f, gg_ = 0.f, go = 0.f;
    if (tid < 64) {
        int tt0 = dir ? 47 : 0;
        const float* Gp = G + (size_t)(tt0 * 16 + ub) * 2048 + dir * 1024 + ujg;
        gi = Gp[0]; gf = Gp[256]; gg_ = Gp[512]; go = Gp[768];
    }

    for (int t = 0; t < 48; ++t) {
        int tt = dir ? (47 - t) : t;
        float* h_out = (t & 1) ? hp : hq;

        if (t > 0) {
            const float* h_in = (t & 1) ? hq : hp;
            const float4* hin4 = reinterpret_cast<const float4*>(h_in + dir * 4096);
#pragma unroll
            for (int i = 0; i < 8; ++i) sm4[tid + i * 128] = hin4[tid + i * 128];
            __syncthreads();

            float acc[64];
#pragma unroll
            for (int i = 0; i < 64; ++i) acc[i] = 0.f;
#pragma unroll
            for (int it = 0; it < 2; ++it) {
                int k4 = it * 32 + kc;
#pragma unroll
                for (int b = 0; b < 16; ++b) {
                    float4 hv = sm4[b * 64 + k4];
                    acc[0 * 16 + b] += wr[it][0].x * hv.x + wr[it][0].y * hv.y + wr[it][0].z * hv.z + wr[it][0].w * hv.w;
                    acc[1 * 16 + b] += wr[it][1].x * hv.x + wr[it][1].y * hv.y + wr[it][1].z * hv.z + wr[it][1].w * hv.w;
                    acc[2 * 16 + b] += wr[it][2].x * hv.x + wr[it][2].y * hv.y + wr[it][2].z * hv.z + wr[it][2].w * hv.w;
                    acc[3 * 16 + b] += wr[it][3].x * hv.x + wr[it][3].y * hv.y + wr[it][3].z * hv.z + wr[it][3].w * hv.w;
                }
            }
            __syncthreads();
#pragma unroll
            for (int gg = 0; gg < 4; ++gg)
#pragma unroll
                for (int b = 0; b < 16; ++b)
                    sm[((ty * 4 + gg) * 16 + b) * 33 + kc] = acc[gg * 16 + b];
            __syncthreads();
#pragma unroll
            for (int rr = 0; rr < 2; ++rr) {
                int o = tid + rr * 128;
                float ss = 0.f;
#pragma unroll
                for (int q = 0; q < 32; ++q) ss += sm[o * 33 + q];
                redout[o] = ss;
            }
        } else {
#pragma unroll
            for (int rr = 0; rr < 2; ++rr) redout[tid + rr * 128] = 0.f;
        }
        __syncthreads();

        if (tid < 64) {
            float ip = redout[(ujj * 4 + 0) * 16 + ub] + gi;
            float fp = redout[(ujj * 4 + 1) * 16 + ub] + gf;
            float gp = redout[(ujj * 4 + 2) * 16 + ub] + gg_;
            float op = redout[(ujj * 4 + 3) * 16 + ub] + go;
            float c = sigm(fp) * c_sm[tid] + sigm(ip) * tanhf(gp);
            c_sm[tid] = c;
            float h = sigm(op) * tanhf(c);
            h_out[dir * 4096 + ub * 256 + ujg] = h;
            xs_out[(size_t)(tt * 16 + ub) * 512 + dir * 256 + ujg] = h;
            if (t == 47) {
                dh[ub * 512 + dir * 256 + ujg] = h;
                dc[ub * 512 + dir * 256 + ujg] = c;
            }
        }
        if (t < 47) {
            if (tid < 64) {
                int ttn = dir ? (47 - (t + 1)) : (t + 1);
                const float* Gp = G + (size_t)(ttn * 16 + ub) * 2048 + dir * 1024 + ujg;
                gi = Gp[0]; gf = Gp[256]; gg_ = Gp[512]; go = Gp[768];
            }
            grid_barD(cnt, gen, base + 1 + t, 64u);
        }
    }
}

// ======================= decoder wavefront v3: 8-deep LDG prefetch ring ====
#define FMA2(acc, wv, xv) asm("fma.rn.f32x2 %0, %1, %2, %0;" : "+l"(acc) : "l"(wv), "l"(xv))
#define LDG_CG_V2(lo, hi, ptr) \
    asm("ld.global.cg.v2.u64 {%0,%1},[%2];" : "=l"(lo), "=l"(hi) : "l"(ptr))
__global__ __launch_bounds__(256, 1) void dec_wave_k(
    const unsigned long long* __restrict__ WT,
    const float* __restrict__ bias,
    const float* __restrict__ dh, const float* __restrict__ dc) {
    __shared__ unsigned long long xh[2176 * 2];    // xbuf[128][17], hbuf[128][17]
    __shared__ float c_sm[1024];
    __shared__ unsigned s_base;
    float* pre = reinterpret_cast<float*>(xh);     // overlay on xbuf: [256 rows][17]

    int tid = threadIdx.x;
    int l = blockIdx.x >> 3, s = blockIdx.x & 7;
    int rp = tid & 127;
    int kh = tid >> 7;

    int g0 = (2 * rp) >> 6;
    int rl0 = (2 * rp) & 63;
    int rowg = g0 * 512 + s * 64 + rl0;
    float bv0 = bias[l * 2048 + rowg];
    float bv1 = bias[l * 2048 + rowg + 1];

    for (int i = tid; i < 1024; i += 256) {
        int jj = i >> 4, b = i & 15;
        c_sm[i] = dc[(size_t)l * 8192 + b * 512 + s * 64 + jj];
    }
    unsigned* cnt = &g_syn[1024];
    unsigned* gen = &g_syn[1025];
    if (tid == 0) s_base = *(volatile unsigned*)gen;
    __syncthreads();
    unsigned base = s_base;

    const float* dsl = g_dsb + (size_t)l * 393216;
    float* dslo = g_dsb + (size_t)(l + 1) * 393216;
    const float* h0 = dh + (size_t)l * 8192;

    int sb = tid >> 4, si = tid & 15;
    unsigned long long* xbuf = xh;
    unsigned long long* hbuf = xh + 2176;
    unsigned long long* mybuf = kh ? hbuf : xbuf;

    const unsigned long long* WTb = WT + ((size_t)l * 524288 + (size_t)s * 128 + (size_t)rp) * 2;

    for (int w = 0; w < 63; ++w) {
        int t = w - l;
        if (t >= 0 && t < 48) {
            unsigned long long acc0[16], acc1[16];
#pragma unroll
            for (int b = 0; b < 16; ++b) { acc0[b] = 0ull; acc1[b] = 0ull; }

            const float* xsrc = dsl + (size_t)t * 8192;
            // h source: layer 15 writes its output in (b*48+t)-row layout,
            // so its own recurrent reads must use that layout too.
            const float* hsrc;
            size_t hstr;
            if (t == 0)        { hsrc = h0;                               hstr = 512;   }
            else if (l == 15)  { hsrc = dslo + (size_t)(t - 1) * 512;     hstr = 24576; }
            else               { hsrc = dslo + (size_t)(t - 1) * 8192;    hstr = 512;   }

#pragma unroll 1
            for (int half = 0; half < 2; ++half) {
                __syncthreads();
#pragma unroll
                for (int i = 0; i < 8; ++i) {
                    int kp = si + i * 16;
                    xbuf[kp * 17 + sb] = *reinterpret_cast<const unsigned long long*>(
                        xsrc + (size_t)sb * 512 + half * 256 + kp * 2);
                    hbuf[kp * 17 + sb] = *reinterpret_cast<const unsigned long long*>(
                        hsrc + (size_t)sb * hstr + half * 256 + kp * 2);
                }
                __syncthreads();

                const unsigned long long* wp = WTb + (size_t)(kh * 256 + half * 128) * 2048;
                unsigned long long wrx[8], wry[8];
#pragma unroll
                for (int i = 0; i < 8; ++i) LDG_CG_V2(wrx[i], wry[i], wp + (size_t)i * 2048);
#pragma unroll 8
                for (int kq = 0; kq < 120; ++kq) {
                    unsigned long long wa = wrx[kq & 7], wb_ = wry[kq & 7];
                    LDG_CG_V2(wrx[kq & 7], wry[kq & 7], wp + (size_t)(kq + 8) * 2048);
                    int p = kq * 17;
#pragma unroll
                    for (int b = 0; b < 16; ++b) {
                        unsigned long long xv = mybuf[p + b];
                        FMA2(acc0[b], wa, xv);
                        FMA2(acc1[b], wb_, xv);
                    }
                }
#pragma unroll
                for (int kq = 120; kq < 128; ++kq) {
                    unsigned long long wa = wrx[kq & 7], wb_ = wry[kq & 7];
                    int p = kq * 17;
#pragma unroll
                    for (int b = 0; b < 16; ++b) {
                        unsigned long long xv = mybuf[p + b];
                        FMA2(acc0[b], wa, xv);
                        FMA2(acc1[b], wb_, xv);
                    }
                }
            }
            __syncthreads();                       // buffer reads done; overlay pre

            int pr0 = (2 * rp) * 17, pr1 = (2 * rp + 1) * 17;
            if (kh == 0) {
#pragma unroll
                for (int b = 0; b < 16; ++b) {
                    float lo, hi;
                    asm("mov.b64 {%0,%1}, %2;" : "=f"(lo), "=f"(hi) : "l"(acc0[b]));
                    pre[pr0 + b] = lo + hi;
                    asm("mov.b64 {%0,%1}, %2;" : "=f"(lo), "=f"(hi) : "l"(acc1[b]));
                    pre[pr1 + b] = lo + hi;
                }
            }
            __syncthreads();
            if (kh == 1) {
#pragma unroll
                for (int b = 0; b < 16; ++b) {
                    float lo, hi;
                    asm("mov.b64 {%0,%1}, %2;" : "=f"(lo), "=f"(hi) : "l"(acc0[b]));
                    pre[pr0 + b] += lo + hi + bv0;
                    asm("mov.b64 {%0,%1}, %2;" : "=f"(lo), "=f"(hi) : "l"(acc1[b]));
                    pre[pr1 + b] += lo + hi + bv1;
                }
            }
            __syncthreads();
#pragma unroll
            for (int q = 0; q < 4; ++q) {
                int idx = tid + q * 256;
                int jj = idx >> 4, b = idx & 15;
                float ip = pre[(jj) * 17 + b];
                float fp = pre[(64 + jj) * 17 + b];
                float gp = pre[(128 + jj) * 17 + b];
                float op = pre[(192 + jj) * 17 + b];
                float c = sigm(fp) * c_sm[idx] + sigm(ip) * tanhf(gp);
                c_sm[idx] = c;
                float h = sigm(op) * tanhf(c);
                if (l == 15)                       // final layer: (b*48+t) row layout
                    dslo[(size_t)b * 24576 + (size_t)t * 512 + s * 64 + jj] = h;
                else
                    dslo[(size_t)t * 8192 + b * 512 + s * 64 + jj] = h;
            }
        }
        if (w < 62) grid_barD(cnt, gen, base + 1 + w, 128u);
    }
}

// ---------------- launch sequence ----------------
extern "C" void kernel_launch(void* const* d_in, const int* in_sizes, int n_in,
                              void* d_out, int out_size) {
    const int*   x        = (const int*)d_in[0];
    const int*   y        = (const int*)d_in[1];
    const float* enc_emb  = (const float*)d_in[2];
    const float* enc_Wih  = (const float*)d_in[3];
    const float* enc_Whh  = (const float*)d_in[4];
    const float* enc_b    = (const float*)d_in[5];
    const float* dec_emb  = (const float*)d_in[6];
    const float* dec_Wih  = (const float*)d_in[7];
    const float* dec_Whh  = (const float*)d_in[8];
    const float* dec_b    = (const float*)d_in[9];
    const float* lin_W    = (const float*)d_in[10];
    const float* lin_b    = (const float*)d_in[11];
    float* out = (float*)d_out;

    float *act0, *act1, *G, *hp, *hq, *dh, *dc, *dsb;
    unsigned long long* WT;
    cudaGetSymbolAddress((void**)&act0, g_act0);
    cudaGetSymbolAddress((void**)&act1, g_act1);
    cudaGetSymbolAddress((void**)&G,    g_G);
    cudaGetSymbolAddress((void**)&hp,   g_hping);
    cudaGetSymbolAddress((void**)&hq,   g_hpong);
    cudaGetSymbolAddress((void**)&dh,   g_dech0);
    cudaGetSymbolAddress((void**)&dc,   g_decc0);
    cudaGetSymbolAddress((void**)&dsb,  g_dsb);
    cudaGetSymbolAddress((void**)&WT,   g_WT);
    float* bufs[2] = {act0, act1};

    // ---- one-time decoder weight transpose ----
    transpose_w_k<<<4096, 256>>>(dec_Wih, dec_Whh, WT);

    // ---- encoder ----
    embed_k<<<768, 128>>>(enc_emb, x, bufs[0]);
    int p = 0;
    for (int l = 0; l < NL; ++l) {
        gemm_k<<<dim3(32, 12), 256>>>(bufs[p], enc_Wih + (size_t)l * 1024 * 1024,
                                      enc_b + l * 2048, G,
                                      (size_t)2048, (size_t)32768, (size_t)1);
        enc_layer_k<<<128, 128>>>(enc_Whh + (size_t)l * 2 * 1024 * 256, G,
                                  bufs[1 - p], hp, hq,
                                  dh + l * 8192, dc + l * 8192);
        p ^= 1;
    }

    // ---- decoder: embed + single wavefront kernel ----
    embed_k<<<768, 128>>>(dec_emb, y, dsb);
    dec_wave_k<<<128, 256>>>(WT, dec_b, dh, dc);

    // ---- final projection (coalesced) on g_dsb[16] ----
    proj_k<<<dim3(500, 12), 256>>>(dsb + (size_t)16 * 393216, lin_W, lin_b, out);
}